// round 12
// baseline (speedup 1.0000x reference)
#include <cuda_runtime.h>
#include <math.h>

// ---------------------------------------------------------------------------
// Problem constants
// ---------------------------------------------------------------------------
#define NTOK   2048
#define DMODEL 1024
#define RANK   512
#define NHEADS 8
#define DHEAD  64
#define NC     64
#define KC     8
#define KE     4

// attention-kernel layout (round-8 known-good)
#define APITCH 36
#define BP128  136
#define BP64   72
#define SCORES_SMEM_W (2 * 128 * APITCH + 2 * 32 * BP128)
#define PV_SMEM_W     (2 * 256 * APITCH + 2 * 32 * BP64)

// GEMM v5: fragment-grouped planes (uint4 groups), raw staging buffers
#define AGP      20                   // A groups per row (16 used + 4 pad); 20%8=4 -> frag conflict-free
#define BCOLP    130                  // B col pitch (128 + 2 pad); 130%8=2 -> frag conflict-free
#define A_GROUPS (128 * AGP)          // 2560 uint4
#define B_GROUPS (16 * BCOLP)         // 2080 uint4
#define RA_W     (128 * APITCH)       // 4608 words raw A
#define RB_W     (32 * BP128)         // 4352 words raw B
#define GEMM_SMEM_W (4 * A_GROUPS + 4 * B_GROUPS + RA_W + RB_W + 256)  // 27776 words = 111.1 KB

// ---------------------------------------------------------------------------
// Device scratch
// ---------------------------------------------------------------------------
__device__ float g_qkv[3 * NTOK * RANK];
__device__ float g_attn[NTOK * RANK];
__device__ float g_scores[16 * 1024 * 1024];
__device__ int   g_cnt_c[3 * NC];
__device__ int   g_list_c[3 * NC * NTOK];
__device__ float g_wt_c[3 * NC * NTOK];
__device__ int   g_cnt_e[NC];
__device__ int   g_list_e[NC * NTOK];
__device__ float g_wt_e[NC * NTOK];

// ---------------------------------------------------------------------------
// tf32 helpers: 3xTF32 split  f = hi + lo
// ---------------------------------------------------------------------------
__device__ __forceinline__ unsigned f2tf(float f) {
    unsigned u; asm("cvt.rna.tf32.f32 %0, %1;" : "=r"(u) : "f"(f)); return u;
}
__device__ __forceinline__ void st_split(unsigned* hi, unsigned* lo, float f) {
    const unsigned h = f2tf(f);
    *hi = h;
    *lo = f2tf(f - __uint_as_float(h));
}
__device__ __forceinline__ void split4(float4 v, uint4& hi, uint4& lo) {
    hi.x = f2tf(v.x); hi.y = f2tf(v.y); hi.z = f2tf(v.z); hi.w = f2tf(v.w);
    lo.x = f2tf(v.x - __uint_as_float(hi.x));
    lo.y = f2tf(v.y - __uint_as_float(hi.y));
    lo.z = f2tf(v.z - __uint_as_float(hi.z));
    lo.w = f2tf(v.w - __uint_as_float(hi.w));
}
__device__ __forceinline__ void rsplit(float v, unsigned& hi, unsigned& lo) {
    hi = f2tf(v);
    lo = f2tf(v - __uint_as_float(hi));
}

__device__ __forceinline__ void mma8(float* c, unsigned a0, unsigned a1,
                                     unsigned a2, unsigned a3,
                                     unsigned b0, unsigned b1) {
    asm volatile(
        "mma.sync.aligned.m16n8k8.row.col.f32.tf32.tf32.f32 "
        "{%0,%1,%2,%3},{%4,%5,%6,%7},{%8,%9},{%0,%1,%2,%3};"
        : "+f"(c[0]), "+f"(c[1]), "+f"(c[2]), "+f"(c[3])
        : "r"(a0), "r"(a1), "r"(a2), "r"(a3), "r"(b0), "r"(b1));
}

__device__ __forceinline__ void cpa16(void* dst, const void* src) {
    unsigned d = (unsigned)__cvta_generic_to_shared(dst);
    asm volatile("cp.async.cg.shared.global [%0], [%1], 16;" :: "r"(d), "l"(src) : "memory");
}
__device__ __forceinline__ void cp_commit() {
    asm volatile("cp.async.commit_group;" ::: "memory");
}
__device__ __forceinline__ void cp_wait0() {
    asm volatile("cp.async.wait_group 0;" ::: "memory");
}

// ---------------------------------------------------------------------------
// K=32 stage from fragment-grouped planes; warp m32 x n64; 3xTF32.
// Ag group (r, ksg, tig) = {hi(8ksg+tig) , hi(+4), lo, lo} of row r.
// Bg group (ksg, tig, col) = {bh(8ksg+tig,col), bh(+4,col), bl, bl}.
// Arithmetic identical to round-8 plane path.
// ---------------------------------------------------------------------------
__device__ __forceinline__ void compute_stage_fg(
    const uint4* __restrict__ Ag, const uint4* __restrict__ Bg,
    float acc[2][8][4], int wm, int wn, int gid, int tig)
{
    #pragma unroll
    for (int ks = 0; ks < 4; ++ks) {
        uint4 fa[2][2];
        #pragma unroll
        for (int m = 0; m < 2; ++m) {
            fa[m][0] = Ag[(wm * 32 + m * 16 + gid)     * AGP + ks * 4 + tig];
            fa[m][1] = Ag[(wm * 32 + m * 16 + gid + 8) * AGP + ks * 4 + tig];
        }
        #pragma unroll
        for (int t = 0; t < 8; ++t) {
            const uint4 fb = Bg[(ks * 4 + tig) * BCOLP + wn * 64 + t * 8 + gid];
            #pragma unroll
            for (int m = 0; m < 2; ++m) {
                mma8(acc[m][t], fa[m][0].x, fa[m][1].x, fa[m][0].y, fa[m][1].y, fb.z, fb.w); // hi*lo
                mma8(acc[m][t], fa[m][0].z, fa[m][1].z, fa[m][0].w, fa[m][1].w, fb.x, fb.y); // lo*hi
                mma8(acc[m][t], fa[m][0].x, fa[m][1].x, fa[m][0].y, fa[m][1].y, fb.x, fb.y); // hi*hi
            }
        }
    }
}

// K=32 stage for attention kernels (round-8 known-good path)
template<int AROWS, int BP>
__device__ __forceinline__ void compute_stage64(
    const unsigned* __restrict__ As, const unsigned* __restrict__ Bs,
    float acc[2][8][4], int wm, int wn, int gid, int tig)
{
    const int AO = AROWS * APITCH, BO = 32 * BP;
    #pragma unroll
    for (int ks = 0; ks < 4; ++ks) {
        const int k0 = ks * 8;
        unsigned ah[2][4], al[2][4];
        #pragma unroll
        for (int m = 0; m < 2; ++m) {
            const int r0 = (wm * 32 + m * 16 + gid) * APITCH + k0;
            const int r1 = (wm * 32 + m * 16 + gid + 8) * APITCH + k0;
            ah[m][0] = As[r0 + tig];          ah[m][1] = As[r1 + tig];
            ah[m][2] = As[r0 + tig + 4];      ah[m][3] = As[r1 + tig + 4];
            al[m][0] = As[AO + r0 + tig];     al[m][1] = As[AO + r1 + tig];
            al[m][2] = As[AO + r0 + tig + 4]; al[m][3] = As[AO + r1 + tig + 4];
        }
        #pragma unroll
        for (int t = 0; t < 8; ++t) {
            const int c0 = (k0 + tig) * BP + wn * 64 + t * 8 + gid;
            const int c1 = c0 + 4 * BP;
            const unsigned bh0 = Bs[c0],      bh1 = Bs[c1];
            const unsigned bl0 = Bs[BO + c0], bl1 = Bs[BO + c1];
            #pragma unroll
            for (int m = 0; m < 2; ++m) {
                mma8(acc[m][t], ah[m][0], ah[m][1], ah[m][2], ah[m][3], bl0, bl1);
                mma8(acc[m][t], al[m][0], al[m][1], al[m][2], al[m][3], bh0, bh1);
                mma8(acc[m][t], ah[m][0], ah[m][1], ah[m][2], ah[m][3], bh0, bh1);
            }
        }
    }
}

// ---------------------------------------------------------------------------
__global__ void k_zero(float* __restrict__ out) {
    const int idx = blockIdx.x * blockDim.x + threadIdx.x;
    const int stride = gridDim.x * blockDim.x;
    for (int i = idx; i < 3 * NTOK * RANK; i += stride) g_qkv[i] = 0.f;
    for (int i = idx; i < NTOK * DMODEL;  i += stride) out[i]   = 0.f;
    if (idx < 3 * NC) g_cnt_c[idx] = 0;
    if (idx < NC)     g_cnt_e[idx] = 0;
}

// ---------------------------------------------------------------------------
// Top-k + softmax + scatter (exact fp32)
// ---------------------------------------------------------------------------
__device__ __forceinline__ void topk_softmax_scatter(
    const float* __restrict__ s, int K, int li_base, int t,
    int* __restrict__ cnt, int* __restrict__ lists, float* __restrict__ wts)
{
    float vals[8]; int idxs[8];
    unsigned long long taken = 0ull;
    for (int kk = 0; kk < K; ++kk) {
        float best = -1e30f; int bi = 0;
        for (int nn = 0; nn < NC; ++nn) {
            const float v = s[nn];
            if (!((taken >> nn) & 1ull) && v > best) { best = v; bi = nn; }
        }
        taken |= 1ull << bi; vals[kk] = best; idxs[kk] = bi;
    }
    const float m = vals[0];
    float ex[8]; float sum = 0.f;
    for (int kk = 0; kk < K; ++kk) { ex[kk] = expf(vals[kk] - m); sum += ex[kk]; }
    const float inv = 1.f / sum;
    for (int kk = 0; kk < K; ++kk) {
        const int li = li_base + idxs[kk];
        const int slot = atomicAdd(&cnt[li], 1);
        lists[(size_t)li * NTOK + slot] = t;
        wts [(size_t)li * NTOK + slot] = ex[kk] * inv;
    }
}

// ---------------------------------------------------------------------------
__global__ __launch_bounds__(256) void k_router_c(
    const float* __restrict__ x, const float* __restrict__ wq,
    const float* __restrict__ wk, const float* __restrict__ wv)
{
    __shared__ float xs[8 * DMODEL];
    __shared__ float sc[8 * 192];
    const int t0 = blockIdx.x * 8;
    const int tid = threadIdx.x;
    for (int i = tid; i < 8 * DMODEL; i += 256) xs[i] = x[(size_t)t0 * DMODEL + i];
    __syncthreads();

    const int warp = tid >> 5, lane = tid & 31;
    const float* wr[3] = { wq, wk, wv };
    for (int j = warp; j < 192; j += 8) {
        const float* wrow = wr[j >> 6] + (size_t)(j & 63) * DMODEL;
        float acc[8] = {0,0,0,0,0,0,0,0};
        for (int i = lane; i < DMODEL; i += 32) {
            const float wv_ = wrow[i];
            #pragma unroll
            for (int tt = 0; tt < 8; ++tt) acc[tt] += xs[tt * DMODEL + i] * wv_;
        }
        #pragma unroll
        for (int tt = 0; tt < 8; ++tt) {
            float v = acc[tt];
            for (int o = 16; o; o >>= 1) v += __shfl_down_sync(0xffffffffu, v, o);
            if (lane == 0) sc[tt * 192 + j] = v;
        }
    }
    __syncthreads();

    if (tid < 24) {
        const int tt = tid / 3, p = tid % 3;
        topk_softmax_scatter(&sc[tt * 192 + p * 64], KC, p * 64, t0 + tt,
                             g_cnt_c, g_list_c, g_wt_c);
    }
}

__global__ __launch_bounds__(256) void k_router_e(const float* __restrict__ wo)
{
    __shared__ float xs[8 * RANK];
    __shared__ float sc[8 * 64];
    const int t0 = blockIdx.x * 8;
    const int tid = threadIdx.x;
    for (int i = tid; i < 8 * RANK; i += 256) xs[i] = g_attn[(size_t)t0 * RANK + i];
    __syncthreads();

    const int warp = tid >> 5, lane = tid & 31;
    for (int j = warp; j < 64; j += 8) {
        const float* wrow = wo + (size_t)j * RANK;
        float acc[8] = {0,0,0,0,0,0,0,0};
        for (int i = lane; i < RANK; i += 32) {
            const float wv_ = wrow[i];
            #pragma unroll
            for (int tt = 0; tt < 8; ++tt) acc[tt] += xs[tt * RANK + i] * wv_;
        }
        #pragma unroll
        for (int tt = 0; tt < 8; ++tt) {
            float v = acc[tt];
            for (int o = 16; o; o >>= 1) v += __shfl_down_sync(0xffffffffu, v, o);
            if (lane == 0) sc[tt * 64 + j] = v;
        }
    }
    __syncthreads();

    if (tid < 8)
        topk_softmax_scatter(&sc[tid * 64], KE, 0, t0 + tid,
                             g_cnt_e, g_list_e, g_wt_e);
}

// ---------------------------------------------------------------------------
// Gathered 3xTF32 MMA GEMM v5: cp.async raw staging (round-8 pipeline),
// split phase writes fragment-grouped planes, frag loads are LDS.128.
// CTA 128 x 128 x 32; 8 warps = 4(m) x 2(n) of m32n64.
// ---------------------------------------------------------------------------
template<int KA, int NOUT>
__device__ __forceinline__ void gemm_scatter_pipe(
    const float* __restrict__ Abase, const float* __restrict__ Bn,
    float* __restrict__ C, const int* __restrict__ tl,
    const float* __restrict__ wl, int c, int cb)
{
    extern __shared__ __align__(16) unsigned smem_g[];
    uint4* Ag   = (uint4*)smem_g;                        // A_GROUPS
    uint4* Bg   = Ag + A_GROUPS;                         // B_GROUPS
    float* rawA = (float*)(Bg + B_GROUPS);               // RA_W
    float* rawB = rawA + RA_W;                           // RB_W
    int*   ts   = (int*)(rawB + RB_W);                   // 128
    float* ws   = (float*)(ts + 128);                    // 128
    const int tid = threadIdx.x, lane = tid & 31, warp = tid >> 5;
    const int wm = warp & 3, wn = warp >> 2;
    const int gid = lane >> 2, tig = lane & 3;
    const int S = KA / 32;

    for (int row0 = 0; row0 < c; row0 += 128) {
        const int rows = min(128, c - row0);
        __syncthreads();               // prior epilogue / raw reads done
        if (tid < 128) {
            ts[tid] = (tid < rows) ? tl[row0 + tid] : 0;
            ws[tid] = (tid < rows) ? wl[row0 + tid] : 0.f;
        }
        __syncthreads();               // ts visible before cp issue

        // prologue: stage 0 loads in flight
        #pragma unroll
        for (int i = 0; i < 4; ++i) {
            const int j = tid + 256 * i, r = j >> 3, q = j & 7;
            cpa16(&rawA[r * APITCH + q * 4],
                  Abase + (size_t)ts[r] * KA + q * 4);
        }
        #pragma unroll
        for (int i = 0; i < 4; ++i) {
            const int j = tid + 256 * i, kk = j >> 5, q = j & 31;
            cpa16(&rawB[kk * BP128 + q * 4],
                  Bn + (size_t)kk * NOUT + cb + q * 4);
        }
        cp_commit();

        float acc[2][8][4] = {};
        for (int s = 0; s < S; ++s) {
            cp_wait0();
            __syncthreads();           // raw[s] visible; planes free

            // split raw -> fragment-grouped planes
            #pragma unroll
            for (int i = 0; i < 2; ++i) {       // A: 512 k-octets
                const int o = tid + 256 * i, r = o >> 2, g = o & 3;
                const float4 v0 = *(const float4*)&rawA[r * APITCH + g * 8];
                const float4 v1 = *(const float4*)&rawA[r * APITCH + g * 8 + 4];
                unsigned h[8], l[8];
                rsplit(v0.x, h[0], l[0]); rsplit(v0.y, h[1], l[1]);
                rsplit(v0.z, h[2], l[2]); rsplit(v0.w, h[3], l[3]);
                rsplit(v1.x, h[4], l[4]); rsplit(v1.y, h[5], l[5]);
                rsplit(v1.z, h[6], l[6]); rsplit(v1.w, h[7], l[7]);
                #pragma unroll
                for (int tg = 0; tg < 4; ++tg)
                    Ag[r * AGP + g * 4 + tg] =
                        make_uint4(h[tg], h[tg + 4], l[tg], l[tg + 4]);
            }
            #pragma unroll
            for (int i = 0; i < 2; ++i) {       // B: 512 (col, ksg) octets
                const int o = tid + 256 * i, col = o & 127, g = o >> 7;
                unsigned h[8], l[8];
                #pragma unroll
                for (int j = 0; j < 8; ++j)
                    rsplit(rawB[(8 * g + j) * BP128 + col], h[j], l[j]);
                #pragma unroll
                for (int tg = 0; tg < 4; ++tg)
                    Bg[(g * 4 + tg) * BCOLP + col] =
                        make_uint4(h[tg], h[tg + 4], l[tg], l[tg + 4]);
            }
            __syncthreads();           // planes ready; raw consumed

            // prefetch stage s+1 (overlaps compute below)
            if (s + 1 < S) {
                const int k0 = (s + 1) * 32;
                #pragma unroll
                for (int i = 0; i < 4; ++i) {
                    const int j = tid + 256 * i, r = j >> 3, q = j & 7;
                    cpa16(&rawA[r * APITCH + q * 4],
                          Abase + (size_t)ts[r] * KA + k0 + q * 4);
                }
                #pragma unroll
                for (int i = 0; i < 4; ++i) {
                    const int j = tid + 256 * i, kk = j >> 5, q = j & 31;
                    cpa16(&rawB[kk * BP128 + q * 4],
                          Bn + (size_t)(k0 + kk) * NOUT + cb + q * 4);
                }
                cp_commit();
            }

            compute_stage_fg(Ag, Bg, acc, wm, wn, gid, tig);
        }

        #pragma unroll
        for (int m = 0; m < 2; ++m)
        #pragma unroll
        for (int i = 0; i < 4; ++i) {
            const int r = wm * 32 + m * 16 + gid + ((i >> 1) ? 8 : 0);
            if (r < rows) {
                const float w = ws[r];
                float* crow = C + (size_t)ts[r] * NOUT + cb;
                #pragma unroll
                for (int t = 0; t < 8; ++t)
                    atomicAdd(&crow[wn * 64 + t * 8 + tig * 2 + (i & 1)],
                              w * acc[m][t][i]);
            }
        }
    }
}

__global__ __launch_bounds__(256) void k_gemm_compress(
    const float* __restrict__ x, const float* __restrict__ cn)
{
    const int li = blockIdx.y;
    const int n  = li & 63;
    gemm_scatter_pipe<DMODEL, RANK>(
        x, cn + (size_t)n * DMODEL * RANK,
        g_qkv + (size_t)(li >> 6) * NTOK * RANK,
        g_list_c + (size_t)li * NTOK, g_wt_c + (size_t)li * NTOK,
        g_cnt_c[li], blockIdx.x * 128);
}

__global__ __launch_bounds__(256) void k_gemm_expand(
    const float* __restrict__ en, float* __restrict__ out)
{
    const int li = blockIdx.y;
    gemm_scatter_pipe<RANK, DMODEL>(
        g_attn, en + (size_t)li * RANK * DMODEL, out,
        g_list_e + (size_t)li * NTOK, g_wt_e + (size_t)li * NTOK,
        g_cnt_e[li], blockIdx.x * 128);
}

// ---------------------------------------------------------------------------
// Attention scores = (Qh Kh^T)/8.  CTA 128x128 (round-8 known-good path)
// ---------------------------------------------------------------------------
__global__ __launch_bounds__(256) void k_attn_scores()
{
    const int bh = blockIdx.z, b = bh >> 3, h = bh & 7;
    const int i0 = blockIdx.y * 128, j0 = blockIdx.x * 128;
    const float* Qb = g_qkv + (size_t)b * 1024 * RANK + h * DHEAD;
    const float* Kb = g_qkv + (size_t)NTOK * RANK + (size_t)b * 1024 * RANK + h * DHEAD;
    extern __shared__ unsigned smemu[];
    unsigned* As = smemu;
    unsigned* Bs = smemu + 2 * 128 * APITCH;
    const int tid = threadIdx.x, lane = tid & 31, warp = tid >> 5;
    const int wm = warp & 3, wn = warp >> 2;
    const int gid = lane >> 2, tig = lane & 3;

    float acc[2][8][4] = {};
    for (int k0 = 0; k0 < DHEAD; k0 += 32) {
        __syncthreads();
        #pragma unroll
        for (int e = tid; e < 1024; e += 256) {
            const int r = e >> 3, q = e & 7;
            const float4 v = *reinterpret_cast<const float4*>(
                Qb + (size_t)(i0 + r) * RANK + k0 + q * 4);
            uint4 hi, lo; split4(v, hi, lo);
            *(uint4*)&As[r * APITCH + q * 4] = hi;
            *(uint4*)&As[128 * APITCH + r * APITCH + q * 4] = lo;
        }
        #pragma unroll
        for (int e = tid; e < 1024; e += 256) {
            const int n = e >> 3, q = e & 7;
            const float4 v = *reinterpret_cast<const float4*>(
                Kb + (size_t)(j0 + n) * RANK + k0 + q * 4);
            st_split(&Bs[(q*4+0)*BP128 + n], &Bs[32*BP128 + (q*4+0)*BP128 + n], v.x);
            st_split(&Bs[(q*4+1)*BP128 + n], &Bs[32*BP128 + (q*4+1)*BP128 + n], v.y);
            st_split(&Bs[(q*4+2)*BP128 + n], &Bs[32*BP128 + (q*4+2)*BP128 + n], v.z);
            st_split(&Bs[(q*4+3)*BP128 + n], &Bs[32*BP128 + (q*4+3)*BP128 + n], v.w);
        }
        __syncthreads();
        compute_stage64<128, BP128>(As, Bs, acc, wm, wn, gid, tig);
    }
    float* outp = g_scores + (size_t)bh * 1024 * 1024;
    #pragma unroll
    for (int m = 0; m < 2; ++m)
    #pragma unroll
    for (int i = 0; i < 4; ++i) {
        const int r = i0 + wm * 32 + m * 16 + gid + ((i >> 1) ? 8 : 0);
        #pragma unroll
        for (int t = 0; t < 8; ++t)
            outp[(size_t)r * 1024 + j0 + wn * 64 + t * 8 + tig * 2 + (i & 1)] =
                acc[m][t][i] * 0.125f;
    }
}

// ---------------------------------------------------------------------------
__global__ __launch_bounds__(256) void k_softmax()
{
    float* p = g_scores + (size_t)blockIdx.x * 1024;
    __shared__ float red[256];
    const int tid = threadIdx.x;
    float m = -1e30f;
    for (int i = tid; i < 1024; i += 256) m = fmaxf(m, p[i]);
    red[tid] = m; __syncthreads();
    for (int s = 128; s; s >>= 1) { if (tid < s) red[tid] = fmaxf(red[tid], red[tid + s]); __syncthreads(); }
    m = red[0]; __syncthreads();
    float sum = 0.f;
    for (int i = tid; i < 1024; i += 256) { const float e = expf(p[i] - m); p[i] = e; sum += e; }
    red[tid] = sum; __syncthreads();
    for (int s = 128; s; s >>= 1) { if (tid < s) red[tid] += red[tid + s]; __syncthreads(); }
    const float inv = 1.f / red[0];
    for (int i = tid; i < 1024; i += 256) p[i] *= inv;
}

// ---------------------------------------------------------------------------
// attn_out = P @ V.  CTA 256x64 (round-8 known-good path)
// ---------------------------------------------------------------------------
__global__ __launch_bounds__(256) void k_attn_pv()
{
    const int bh = blockIdx.y, b = bh >> 3, h = bh & 7;
    const int i0 = blockIdx.x * 256;
    const float* P  = g_scores + (size_t)bh * 1024 * 1024;
    const float* Vb = g_qkv + (size_t)2 * NTOK * RANK + (size_t)b * 1024 * RANK + h * DHEAD;
    extern __shared__ unsigned smemu[];
    unsigned* As = smemu;
    unsigned* Bs = smemu + 2 * 256 * APITCH;
    const int tid = threadIdx.x, lane = tid & 31, warp = tid >> 5;
    const int wm = warp;
    const int gid = lane >> 2, tig = lane & 3;

    float acc[2][8][4] = {};
    for (int k0 = 0; k0 < 1024; k0 += 32) {
        __syncthreads();
        #pragma unroll
        for (int e = tid; e < 2048; e += 256) {
            const int r = e >> 3, q = e & 7;
            const float4 v = *reinterpret_cast<const float4*>(
                P + (size_t)(i0 + r) * 1024 + k0 + q * 4);
            uint4 hi, lo; split4(v, hi, lo);
            *(uint4*)&As[r * APITCH + q * 4] = hi;
            *(uint4*)&As[256 * APITCH + r * APITCH + q * 4] = lo;
        }
        #pragma unroll
        for (int e = tid; e < 512; e += 256) {
            const int kk = e >> 4, q = e & 15;
            const float4 v = *reinterpret_cast<const float4*>(
                Vb + (size_t)(k0 + kk) * RANK + q * 4);
            uint4 hi, lo; split4(v, hi, lo);
            *(uint4*)&Bs[kk * BP64 + q * 4] = hi;
            *(uint4*)&Bs[32 * BP64 + kk * BP64 + q * 4] = lo;
        }
        __syncthreads();
        compute_stage64<256, BP64>(As, Bs, acc, wm, 0, gid, tig);
    }
    #pragma unroll
    for (int m = 0; m < 2; ++m)
    #pragma unroll
    for (int i = 0; i < 4; ++i) {
        const int r = b * 1024 + i0 + wm * 32 + m * 16 + gid + ((i >> 1) ? 8 : 0);
        #pragma unroll
        for (int t = 0; t < 8; ++t)
            g_attn[(size_t)r * RANK + h * DHEAD + t * 8 + tig * 2 + (i & 1)] =
                acc[m][t][i];
    }
}

// ---------------------------------------------------------------------------
extern "C" void kernel_launch(void* const* d_in, const int* in_sizes, int n_in,
                              void* d_out, int out_size)
{
    const float* x  = (const float*)d_in[0];
    const float* cn = (const float*)d_in[2];
    const float* en = (const float*)d_in[3];
    const float* wq = (const float*)d_in[4];
    const float* wk = (const float*)d_in[5];
    const float* wv = (const float*)d_in[6];
    const float* wo = (const float*)d_in[7];
    float* out = (float*)d_out;

    cudaFuncSetAttribute(k_gemm_compress, cudaFuncAttributeMaxDynamicSharedMemorySize, GEMM_SMEM_W * 4);
    cudaFuncSetAttribute(k_gemm_expand,   cudaFuncAttributeMaxDynamicSharedMemorySize, GEMM_SMEM_W * 4);
    cudaFuncSetAttribute(k_attn_scores,   cudaFuncAttributeMaxDynamicSharedMemorySize, SCORES_SMEM_W * 4);
    cudaFuncSetAttribute(k_attn_pv,       cudaFuncAttributeMaxDynamicSharedMemorySize, PV_SMEM_W * 4);

    k_zero<<<2048, 256>>>(out);
    k_router_c<<<NTOK / 8, 256>>>(x, wq, wk, wv);
    k_gemm_compress<<<dim3(4, 192), 256, GEMM_SMEM_W * 4>>>(x, cn);
    k_attn_scores<<<dim3(8, 8, 16), 256, SCORES_SMEM_W * 4>>>();
    k_softmax<<<16384, 256>>>();
    k_attn_pv<<<dim3(4, 16), 256, PV_SMEM_W * 4>>>();
    k_router_e<<<NTOK / 8, 256>>>(wo);
    k_gemm_expand<<<dim3(8, 64), 256, GEMM_SMEM_W * 4>>>(en, out);
}

// round 13
// speedup vs baseline: 1.0695x; 1.0695x over previous
#include <cuda_runtime.h>
#include <math.h>

// ---------------------------------------------------------------------------
// Problem constants
// ---------------------------------------------------------------------------
#define NTOK   2048
#define DMODEL 1024
#define RANK   512
#define NHEADS 8
#define DHEAD  64
#define NC     64
#define KC     8
#define KE     4

// attention-kernel layout (round-8 known-good)
#define APITCH 36
#define BP128  136
#define BP64   72
#define SCORES_SMEM_W (2 * 128 * APITCH + 2 * 32 * BP128)
#define PV_SMEM_W     (2 * 256 * APITCH + 2 * 32 * BP64)

// GEMM v5b: fragment-grouped planes, conflict-free pitches (mod-8 audited)
#define AGP      17                   // uint4/row: 17%8=1 -> frag & STS conflict-free
#define BCOLP    130                  // uint4 col pitch: +gid dominates -> conflict-free
#define A_GROUPS (128 * AGP)          // 2176 uint4
#define B_GROUPS (16 * BCOLP)         // 2080 uint4
#define RA_W     (128 * APITCH)       // 4608 words raw A
#define RB_W     (32 * BP128)         // 4352 words raw B
#define GEMM_SMEM_W (4 * A_GROUPS + 4 * B_GROUPS + RA_W + RB_W + 256)  // 26240 words = 105 KB

// ---------------------------------------------------------------------------
// Device scratch
// ---------------------------------------------------------------------------
__device__ float g_qkv[3 * NTOK * RANK];
__device__ float g_attn[NTOK * RANK];
__device__ float g_scores[16 * 1024 * 1024];
__device__ int   g_cnt_c[3 * NC];
__device__ int   g_list_c[3 * NC * NTOK];
__device__ float g_wt_c[3 * NC * NTOK];
__device__ int   g_cnt_e[NC];
__device__ int   g_list_e[NC * NTOK];
__device__ float g_wt_e[NC * NTOK];

// ---------------------------------------------------------------------------
// tf32 helpers: 3xTF32 split  f = hi + lo
// ---------------------------------------------------------------------------
__device__ __forceinline__ unsigned f2tf(float f) {
    unsigned u; asm("cvt.rna.tf32.f32 %0, %1;" : "=r"(u) : "f"(f)); return u;
}
__device__ __forceinline__ void st_split(unsigned* hi, unsigned* lo, float f) {
    const unsigned h = f2tf(f);
    *hi = h;
    *lo = f2tf(f - __uint_as_float(h));
}
__device__ __forceinline__ void split4(float4 v, uint4& hi, uint4& lo) {
    hi.x = f2tf(v.x); hi.y = f2tf(v.y); hi.z = f2tf(v.z); hi.w = f2tf(v.w);
    lo.x = f2tf(v.x - __uint_as_float(hi.x));
    lo.y = f2tf(v.y - __uint_as_float(hi.y));
    lo.z = f2tf(v.z - __uint_as_float(hi.z));
    lo.w = f2tf(v.w - __uint_as_float(hi.w));
}
__device__ __forceinline__ void rsplit(float v, unsigned& hi, unsigned& lo) {
    hi = f2tf(v);
    lo = f2tf(v - __uint_as_float(hi));
}

__device__ __forceinline__ void mma8(float* c, unsigned a0, unsigned a1,
                                     unsigned a2, unsigned a3,
                                     unsigned b0, unsigned b1) {
    asm volatile(
        "mma.sync.aligned.m16n8k8.row.col.f32.tf32.tf32.f32 "
        "{%0,%1,%2,%3},{%4,%5,%6,%7},{%8,%9},{%0,%1,%2,%3};"
        : "+f"(c[0]), "+f"(c[1]), "+f"(c[2]), "+f"(c[3])
        : "r"(a0), "r"(a1), "r"(a2), "r"(a3), "r"(b0), "r"(b1));
}

__device__ __forceinline__ void cpa16(void* dst, const void* src) {
    unsigned d = (unsigned)__cvta_generic_to_shared(dst);
    asm volatile("cp.async.cg.shared.global [%0], [%1], 16;" :: "r"(d), "l"(src) : "memory");
}
__device__ __forceinline__ void cp_commit() {
    asm volatile("cp.async.commit_group;" ::: "memory");
}
__device__ __forceinline__ void cp_wait0() {
    asm volatile("cp.async.wait_group 0;" ::: "memory");
}

// ---------------------------------------------------------------------------
// K=32 stage from fragment-grouped planes; warp m32 x n64; 3xTF32.
// Ag group (r, ksg, tig) = {hi(8ksg+tig), hi(+4), lo, lo} of row r.
// Bg group (ksg, tig, col) = {bh(8ksg+tig,col), bh(+4,col), bl, bl}.
// Arithmetic identical to round-8 plane path.
// ---------------------------------------------------------------------------
__device__ __forceinline__ void compute_stage_fg(
    const uint4* __restrict__ Ag, const uint4* __restrict__ Bg,
    float acc[2][8][4], int wm, int wn, int gid, int tig)
{
    #pragma unroll
    for (int ks = 0; ks < 4; ++ks) {
        uint4 fa[2][2];
        #pragma unroll
        for (int m = 0; m < 2; ++m) {
            fa[m][0] = Ag[(wm * 32 + m * 16 + gid)     * AGP + ks * 4 + tig];
            fa[m][1] = Ag[(wm * 32 + m * 16 + gid + 8) * AGP + ks * 4 + tig];
        }
        #pragma unroll
        for (int t = 0; t < 8; ++t) {
            const uint4 fb = Bg[(ks * 4 + tig) * BCOLP + wn * 64 + t * 8 + gid];
            #pragma unroll
            for (int m = 0; m < 2; ++m) {
                mma8(acc[m][t], fa[m][0].x, fa[m][1].x, fa[m][0].y, fa[m][1].y, fb.z, fb.w); // hi*lo
                mma8(acc[m][t], fa[m][0].z, fa[m][1].z, fa[m][0].w, fa[m][1].w, fb.x, fb.y); // lo*hi
                mma8(acc[m][t], fa[m][0].x, fa[m][1].x, fa[m][0].y, fa[m][1].y, fb.x, fb.y); // hi*hi
            }
        }
    }
}

// K=32 stage for attention kernels (round-8 known-good path)
template<int AROWS, int BP>
__device__ __forceinline__ void compute_stage64(
    const unsigned* __restrict__ As, const unsigned* __restrict__ Bs,
    float acc[2][8][4], int wm, int wn, int gid, int tig)
{
    const int AO = AROWS * APITCH, BO = 32 * BP;
    #pragma unroll
    for (int ks = 0; ks < 4; ++ks) {
        const int k0 = ks * 8;
        unsigned ah[2][4], al[2][4];
        #pragma unroll
        for (int m = 0; m < 2; ++m) {
            const int r0 = (wm * 32 + m * 16 + gid) * APITCH + k0;
            const int r1 = (wm * 32 + m * 16 + gid + 8) * APITCH + k0;
            ah[m][0] = As[r0 + tig];          ah[m][1] = As[r1 + tig];
            ah[m][2] = As[r0 + tig + 4];      ah[m][3] = As[r1 + tig + 4];
            al[m][0] = As[AO + r0 + tig];     al[m][1] = As[AO + r1 + tig];
            al[m][2] = As[AO + r0 + tig + 4]; al[m][3] = As[AO + r1 + tig + 4];
        }
        #pragma unroll
        for (int t = 0; t < 8; ++t) {
            const int c0 = (k0 + tig) * BP + wn * 64 + t * 8 + gid;
            const int c1 = c0 + 4 * BP;
            const unsigned bh0 = Bs[c0],      bh1 = Bs[c1];
            const unsigned bl0 = Bs[BO + c0], bl1 = Bs[BO + c1];
            #pragma unroll
            for (int m = 0; m < 2; ++m) {
                mma8(acc[m][t], ah[m][0], ah[m][1], ah[m][2], ah[m][3], bl0, bl1);
                mma8(acc[m][t], al[m][0], al[m][1], al[m][2], al[m][3], bh0, bh1);
                mma8(acc[m][t], ah[m][0], ah[m][1], ah[m][2], ah[m][3], bh0, bh1);
            }
        }
    }
}

// ---------------------------------------------------------------------------
__global__ void k_zero(float* __restrict__ out) {
    const int idx = blockIdx.x * blockDim.x + threadIdx.x;
    const int stride = gridDim.x * blockDim.x;
    for (int i = idx; i < 3 * NTOK * RANK; i += stride) g_qkv[i] = 0.f;
    for (int i = idx; i < NTOK * DMODEL;  i += stride) out[i]   = 0.f;
    if (idx < 3 * NC) g_cnt_c[idx] = 0;
    if (idx < NC)     g_cnt_e[idx] = 0;
}

// ---------------------------------------------------------------------------
// Top-k + softmax + scatter (exact fp32)
// ---------------------------------------------------------------------------
__device__ __forceinline__ void topk_softmax_scatter(
    const float* __restrict__ s, int K, int li_base, int t,
    int* __restrict__ cnt, int* __restrict__ lists, float* __restrict__ wts)
{
    float vals[8]; int idxs[8];
    unsigned long long taken = 0ull;
    for (int kk = 0; kk < K; ++kk) {
        float best = -1e30f; int bi = 0;
        for (int nn = 0; nn < NC; ++nn) {
            const float v = s[nn];
            if (!((taken >> nn) & 1ull) && v > best) { best = v; bi = nn; }
        }
        taken |= 1ull << bi; vals[kk] = best; idxs[kk] = bi;
    }
    const float m = vals[0];
    float ex[8]; float sum = 0.f;
    for (int kk = 0; kk < K; ++kk) { ex[kk] = expf(vals[kk] - m); sum += ex[kk]; }
    const float inv = 1.f / sum;
    for (int kk = 0; kk < K; ++kk) {
        const int li = li_base + idxs[kk];
        const int slot = atomicAdd(&cnt[li], 1);
        lists[(size_t)li * NTOK + slot] = t;
        wts [(size_t)li * NTOK + slot] = ex[kk] * inv;
    }
}

// ---------------------------------------------------------------------------
__global__ __launch_bounds__(256) void k_router_c(
    const float* __restrict__ x, const float* __restrict__ wq,
    const float* __restrict__ wk, const float* __restrict__ wv)
{
    __shared__ float xs[8 * DMODEL];
    __shared__ float sc[8 * 192];
    const int t0 = blockIdx.x * 8;
    const int tid = threadIdx.x;
    for (int i = tid; i < 8 * DMODEL; i += 256) xs[i] = x[(size_t)t0 * DMODEL + i];
    __syncthreads();

    const int warp = tid >> 5, lane = tid & 31;
    const float* wr[3] = { wq, wk, wv };
    for (int j = warp; j < 192; j += 8) {
        const float* wrow = wr[j >> 6] + (size_t)(j & 63) * DMODEL;
        float acc[8] = {0,0,0,0,0,0,0,0};
        for (int i = lane; i < DMODEL; i += 32) {
            const float wv_ = wrow[i];
            #pragma unroll
            for (int tt = 0; tt < 8; ++tt) acc[tt] += xs[tt * DMODEL + i] * wv_;
        }
        #pragma unroll
        for (int tt = 0; tt < 8; ++tt) {
            float v = acc[tt];
            for (int o = 16; o; o >>= 1) v += __shfl_down_sync(0xffffffffu, v, o);
            if (lane == 0) sc[tt * 192 + j] = v;
        }
    }
    __syncthreads();

    if (tid < 24) {
        const int tt = tid / 3, p = tid % 3;
        topk_softmax_scatter(&sc[tt * 192 + p * 64], KC, p * 64, t0 + tt,
                             g_cnt_c, g_list_c, g_wt_c);
    }
}

__global__ __launch_bounds__(256) void k_router_e(const float* __restrict__ wo)
{
    __shared__ float xs[8 * RANK];
    __shared__ float sc[8 * 64];
    const int t0 = blockIdx.x * 8;
    const int tid = threadIdx.x;
    for (int i = tid; i < 8 * RANK; i += 256) xs[i] = g_attn[(size_t)t0 * RANK + i];
    __syncthreads();

    const int warp = tid >> 5, lane = tid & 31;
    for (int j = warp; j < 64; j += 8) {
        const float* wrow = wo + (size_t)j * RANK;
        float acc[8] = {0,0,0,0,0,0,0,0};
        for (int i = lane; i < RANK; i += 32) {
            const float wv_ = wrow[i];
            #pragma unroll
            for (int tt = 0; tt < 8; ++tt) acc[tt] += xs[tt * RANK + i] * wv_;
        }
        #pragma unroll
        for (int tt = 0; tt < 8; ++tt) {
            float v = acc[tt];
            for (int o = 16; o; o >>= 1) v += __shfl_down_sync(0xffffffffu, v, o);
            if (lane == 0) sc[tt * 64 + j] = v;
        }
    }
    __syncthreads();

    if (tid < 8)
        topk_softmax_scatter(&sc[tid * 64], KE, 0, t0 + tid,
                             g_cnt_e, g_list_e, g_wt_e);
}

// ---------------------------------------------------------------------------
// Gathered 3xTF32 MMA GEMM v5b: cp.async raw staging (round-8 pipeline),
// split writes fragment-grouped planes (conflict-free), frag loads LDS.128.
// CTA 128 x 128 x 32; 8 warps = 4(m) x 2(n) of m32n64.
// ---------------------------------------------------------------------------
template<int KA, int NOUT>
__device__ __forceinline__ void gemm_scatter_pipe(
    const float* __restrict__ Abase, const float* __restrict__ Bn,
    float* __restrict__ C, const int* __restrict__ tl,
    const float* __restrict__ wl, int c, int cb)
{
    extern __shared__ __align__(16) unsigned smem_g[];
    uint4* Ag   = (uint4*)smem_g;                        // A_GROUPS
    uint4* Bg   = Ag + A_GROUPS;                         // B_GROUPS
    float* rawA = (float*)(Bg + B_GROUPS);               // RA_W
    float* rawB = rawA + RA_W;                           // RB_W
    int*   ts   = (int*)(rawB + RB_W);                   // 128
    float* ws   = (float*)(ts + 128);                    // 128
    const int tid = threadIdx.x, lane = tid & 31, warp = tid >> 5;
    const int wm = warp & 3, wn = warp >> 2;
    const int gid = lane >> 2, tig = lane & 3;
    const int S = KA / 32;

    for (int row0 = 0; row0 < c; row0 += 128) {
        const int rows = min(128, c - row0);
        __syncthreads();               // prior epilogue / raw reads done
        if (tid < 128) {
            ts[tid] = (tid < rows) ? tl[row0 + tid] : 0;
            ws[tid] = (tid < rows) ? wl[row0 + tid] : 0.f;
        }
        __syncthreads();               // ts visible before cp issue

        // prologue: stage 0 loads in flight
        #pragma unroll
        for (int i = 0; i < 4; ++i) {
            const int j = tid + 256 * i, r = j >> 3, q = j & 7;
            cpa16(&rawA[r * APITCH + q * 4],
                  Abase + (size_t)ts[r] * KA + q * 4);
        }
        #pragma unroll
        for (int i = 0; i < 4; ++i) {
            const int j = tid + 256 * i, kk = j >> 5, q = j & 31;
            cpa16(&rawB[kk * BP128 + q * 4],
                  Bn + (size_t)kk * NOUT + cb + q * 4);
        }
        cp_commit();

        float acc[2][8][4] = {};
        for (int s = 0; s < S; ++s) {
            cp_wait0();
            __syncthreads();           // raw[s] visible; planes free

            // split raw -> fragment-grouped planes
            // A: 512 k-octets; r = o&127 (warp-consecutive -> conflict-free
            // LDS.128 and STS.128), g = o>>7.
            #pragma unroll
            for (int i = 0; i < 2; ++i) {
                const int o = tid + 256 * i, r = o & 127, g = o >> 7;
                const float4 v0 = *(const float4*)&rawA[r * APITCH + g * 8];
                const float4 v1 = *(const float4*)&rawA[r * APITCH + g * 8 + 4];
                unsigned h[8], l[8];
                rsplit(v0.x, h[0], l[0]); rsplit(v0.y, h[1], l[1]);
                rsplit(v0.z, h[2], l[2]); rsplit(v0.w, h[3], l[3]);
                rsplit(v1.x, h[4], l[4]); rsplit(v1.y, h[5], l[5]);
                rsplit(v1.z, h[6], l[6]); rsplit(v1.w, h[7], l[7]);
                #pragma unroll
                for (int tg = 0; tg < 4; ++tg)
                    Ag[r * AGP + g * 4 + tg] =
                        make_uint4(h[tg], h[tg + 4], l[tg], l[tg + 4]);
            }
            #pragma unroll
            for (int i = 0; i < 2; ++i) {       // B: 512 (col, ksg) octets
                const int o = tid + 256 * i, col = o & 127, g = o >> 7;
                unsigned h[8], l[8];
                #pragma unroll
                for (int j = 0; j < 8; ++j)
                    rsplit(rawB[(8 * g + j) * BP128 + col], h[j], l[j]);
                #pragma unroll
                for (int tg = 0; tg < 4; ++tg)
                    Bg[(g * 4 + tg) * BCOLP + col] =
                        make_uint4(h[tg], h[tg + 4], l[tg], l[tg + 4]);
            }
            __syncthreads();           // planes ready; raw consumed

            // prefetch stage s+1 (overlaps compute below)
            if (s + 1 < S) {
                const int k0 = (s + 1) * 32;
                #pragma unroll
                for (int i = 0; i < 4; ++i) {
                    const int j = tid + 256 * i, r = j >> 3, q = j & 7;
                    cpa16(&rawA[r * APITCH + q * 4],
                          Abase + (size_t)ts[r] * KA + k0 + q * 4);
                }
                #pragma unroll
                for (int i = 0; i < 4; ++i) {
                    const int j = tid + 256 * i, kk = j >> 5, q = j & 31;
                    cpa16(&rawB[kk * BP128 + q * 4],
                          Bn + (size_t)(k0 + kk) * NOUT + cb + q * 4);
                }
                cp_commit();
            }

            compute_stage_fg(Ag, Bg, acc, wm, wn, gid, tig);
        }

        #pragma unroll
        for (int m = 0; m < 2; ++m)
        #pragma unroll
        for (int i = 0; i < 4; ++i) {
            const int r = wm * 32 + m * 16 + gid + ((i >> 1) ? 8 : 0);
            if (r < rows) {
                const float w = ws[r];
                float* crow = C + (size_t)ts[r] * NOUT + cb;
                #pragma unroll
                for (int t = 0; t < 8; ++t)
                    atomicAdd(&crow[wn * 64 + t * 8 + tig * 2 + (i & 1)],
                              w * acc[m][t][i]);
            }
        }
    }
}

__global__ __launch_bounds__(256) void k_gemm_compress(
    const float* __restrict__ x, const float* __restrict__ cn)
{
    const int li = blockIdx.y;
    const int n  = li & 63;
    gemm_scatter_pipe<DMODEL, RANK>(
        x, cn + (size_t)n * DMODEL * RANK,
        g_qkv + (size_t)(li >> 6) * NTOK * RANK,
        g_list_c + (size_t)li * NTOK, g_wt_c + (size_t)li * NTOK,
        g_cnt_c[li], blockIdx.x * 128);
}

__global__ __launch_bounds__(256) void k_gemm_expand(
    const float* __restrict__ en, float* __restrict__ out)
{
    const int li = blockIdx.y;
    gemm_scatter_pipe<RANK, DMODEL>(
        g_attn, en + (size_t)li * RANK * DMODEL, out,
        g_list_e + (size_t)li * NTOK, g_wt_e + (size_t)li * NTOK,
        g_cnt_e[li], blockIdx.x * 128);
}

// ---------------------------------------------------------------------------
// Attention scores = (Qh Kh^T)/8.  CTA 128x128 (round-8 known-good path)
// ---------------------------------------------------------------------------
__global__ __launch_bounds__(256) void k_attn_scores()
{
    const int bh = blockIdx.z, b = bh >> 3, h = bh & 7;
    const int i0 = blockIdx.y * 128, j0 = blockIdx.x * 128;
    const float* Qb = g_qkv + (size_t)b * 1024 * RANK + h * DHEAD;
    const float* Kb = g_qkv + (size_t)NTOK * RANK + (size_t)b * 1024 * RANK + h * DHEAD;
    extern __shared__ unsigned smemu[];
    unsigned* As = smemu;
    unsigned* Bs = smemu + 2 * 128 * APITCH;
    const int tid = threadIdx.x, lane = tid & 31, warp = tid >> 5;
    const int wm = warp & 3, wn = warp >> 2;
    const int gid = lane >> 2, tig = lane & 3;

    float acc[2][8][4] = {};
    for (int k0 = 0; k0 < DHEAD; k0 += 32) {
        __syncthreads();
        #pragma unroll
        for (int e = tid; e < 1024; e += 256) {
            const int r = e >> 3, q = e & 7;
            const float4 v = *reinterpret_cast<const float4*>(
                Qb + (size_t)(i0 + r) * RANK + k0 + q * 4);
            uint4 hi, lo; split4(v, hi, lo);
            *(uint4*)&As[r * APITCH + q * 4] = hi;
            *(uint4*)&As[128 * APITCH + r * APITCH + q * 4] = lo;
        }
        #pragma unroll
        for (int e = tid; e < 1024; e += 256) {
            const int n = e >> 3, q = e & 7;
            const float4 v = *reinterpret_cast<const float4*>(
                Kb + (size_t)(j0 + n) * RANK + k0 + q * 4);
            st_split(&Bs[(q*4+0)*BP128 + n], &Bs[32*BP128 + (q*4+0)*BP128 + n], v.x);
            st_split(&Bs[(q*4+1)*BP128 + n], &Bs[32*BP128 + (q*4+1)*BP128 + n], v.y);
            st_split(&Bs[(q*4+2)*BP128 + n], &Bs[32*BP128 + (q*4+2)*BP128 + n], v.z);
            st_split(&Bs[(q*4+3)*BP128 + n], &Bs[32*BP128 + (q*4+3)*BP128 + n], v.w);
        }
        __syncthreads();
        compute_stage64<128, BP128>(As, Bs, acc, wm, wn, gid, tig);
    }
    float* outp = g_scores + (size_t)bh * 1024 * 1024;
    #pragma unroll
    for (int m = 0; m < 2; ++m)
    #pragma unroll
    for (int i = 0; i < 4; ++i) {
        const int r = i0 + wm * 32 + m * 16 + gid + ((i >> 1) ? 8 : 0);
        #pragma unroll
        for (int t = 0; t < 8; ++t)
            outp[(size_t)r * 1024 + j0 + wn * 64 + t * 8 + tig * 2 + (i & 1)] =
                acc[m][t][i] * 0.125f;
    }
}

// ---------------------------------------------------------------------------
__global__ __launch_bounds__(256) void k_softmax()
{
    float* p = g_scores + (size_t)blockIdx.x * 1024;
    __shared__ float red[256];
    const int tid = threadIdx.x;
    float m = -1e30f;
    for (int i = tid; i < 1024; i += 256) m = fmaxf(m, p[i]);
    red[tid] = m; __syncthreads();
    for (int s = 128; s; s >>= 1) { if (tid < s) red[tid] = fmaxf(red[tid], red[tid + s]); __syncthreads(); }
    m = red[0]; __syncthreads();
    float sum = 0.f;
    for (int i = tid; i < 1024; i += 256) { const float e = expf(p[i] - m); p[i] = e; sum += e; }
    red[tid] = sum; __syncthreads();
    for (int s = 128; s; s >>= 1) { if (tid < s) red[tid] += red[tid + s]; __syncthreads(); }
    const float inv = 1.f / red[0];
    for (int i = tid; i < 1024; i += 256) p[i] *= inv;
}

// ---------------------------------------------------------------------------
// attn_out = P @ V.  CTA 256x64 (round-8 known-good path)
// ---------------------------------------------------------------------------
__global__ __launch_bounds__(256) void k_attn_pv()
{
    const int bh = blockIdx.y, b = bh >> 3, h = bh & 7;
    const int i0 = blockIdx.x * 256;
    const float* P  = g_scores + (size_t)bh * 1024 * 1024;
    const float* Vb = g_qkv + (size_t)2 * NTOK * RANK + (size_t)b * 1024 * RANK + h * DHEAD;
    extern __shared__ unsigned smemu[];
    unsigned* As = smemu;
    unsigned* Bs = smemu + 2 * 256 * APITCH;
    const int tid = threadIdx.x, lane = tid & 31, warp = tid >> 5;
    const int wm = warp;
    const int gid = lane >> 2, tig = lane & 3;

    float acc[2][8][4] = {};
    for (int k0 = 0; k0 < 1024; k0 += 32) {
        __syncthreads();
        #pragma unroll
        for (int e = tid; e < 2048; e += 256) {
            const int r = e >> 3, q = e & 7;
            const float4 v = *reinterpret_cast<const float4*>(
                P + (size_t)(i0 + r) * 1024 + k0 + q * 4);
            uint4 hi, lo; split4(v, hi, lo);
            *(uint4*)&As[r * APITCH + q * 4] = hi;
            *(uint4*)&As[256 * APITCH + r * APITCH + q * 4] = lo;
        }
        #pragma unroll
        for (int e = tid; e < 512; e += 256) {
            const int kk = e >> 4, q = e & 15;
            const float4 v = *reinterpret_cast<const float4*>(
                Vb + (size_t)(k0 + kk) * RANK + q * 4);
            uint4 hi, lo; split4(v, hi, lo);
            *(uint4*)&Bs[kk * BP64 + q * 4] = hi;
            *(uint4*)&Bs[32 * BP64 + kk * BP64 + q * 4] = lo;
        }
        __syncthreads();
        compute_stage64<256, BP64>(As, Bs, acc, wm, 0, gid, tig);
    }
    #pragma unroll
    for (int m = 0; m < 2; ++m)
    #pragma unroll
    for (int i = 0; i < 4; ++i) {
        const int r = b * 1024 + i0 + wm * 32 + m * 16 + gid + ((i >> 1) ? 8 : 0);
        #pragma unroll
        for (int t = 0; t < 8; ++t)
            g_attn[(size_t)r * RANK + h * DHEAD + t * 8 + tig * 2 + (i & 1)] =
                acc[m][t][i];
    }
}

// ---------------------------------------------------------------------------
extern "C" void kernel_launch(void* const* d_in, const int* in_sizes, int n_in,
                              void* d_out, int out_size)
{
    const float* x  = (const float*)d_in[0];
    const float* cn = (const float*)d_in[2];
    const float* en = (const float*)d_in[3];
    const float* wq = (const float*)d_in[4];
    const float* wk = (const float*)d_in[5];
    const float* wv = (const float*)d_in[6];
    const float* wo = (const float*)d_in[7];
    float* out = (float*)d_out;

    cudaFuncSetAttribute(k_gemm_compress, cudaFuncAttributeMaxDynamicSharedMemorySize, GEMM_SMEM_W * 4);
    cudaFuncSetAttribute(k_gemm_expand,   cudaFuncAttributeMaxDynamicSharedMemorySize, GEMM_SMEM_W * 4);
    cudaFuncSetAttribute(k_attn_scores,   cudaFuncAttributeMaxDynamicSharedMemorySize, SCORES_SMEM_W * 4);
    cudaFuncSetAttribute(k_attn_pv,       cudaFuncAttributeMaxDynamicSharedMemorySize, PV_SMEM_W * 4);

    k_zero<<<2048, 256>>>(out);
    k_router_c<<<NTOK / 8, 256>>>(x, wq, wk, wv);
    k_gemm_compress<<<dim3(4, 192), 256, GEMM_SMEM_W * 4>>>(x, cn);
    k_attn_scores<<<dim3(8, 8, 16), 256, SCORES_SMEM_W * 4>>>();
    k_softmax<<<16384, 256>>>();
    k_attn_pv<<<dim3(4, 16), 256, PV_SMEM_W * 4>>>();
    k_router_e<<<NTOK / 8, 256>>>(wo);
    k_gemm_expand<<<dim3(8, 64), 256, GEMM_SMEM_W * 4>>>(en, out);
}

// round 14
// speedup vs baseline: 1.3338x; 1.2471x over previous
#include <cuda_runtime.h>
#include <math.h>

// ---------------------------------------------------------------------------
// Problem constants
// ---------------------------------------------------------------------------
#define NTOK   2048
#define DMODEL 1024
#define RANK   512
#define NHEADS 8
#define DHEAD  64
#define NC     64
#define KC     8
#define KE     4

#define APITCH 36        // ≡4 (mod 32): A frag banks 4*gid+tig all distinct
#define BP128  136       // ≡8 (mod 32): B frag banks 8*tig+gid all distinct
#define BP64   72        // ≡8 (mod 32), n-tile 64 (PV)

// GEMM smem words: A planes + B planes + rawA + rawB + ts/ws
#define GEMM_SMEM_W   (2 * 128 * APITCH + 2 * 32 * BP128 + 128 * APITCH + 32 * 128 + 256)
#define SCORES_SMEM_W (2 * 128 * APITCH + 2 * 32 * BP128)
#define PV_SMEM_W     (2 * 256 * APITCH + 2 * 32 * BP64)

// ---------------------------------------------------------------------------
// Device scratch
// ---------------------------------------------------------------------------
__device__ float g_qkv[3 * NTOK * RANK];
__device__ float g_attn[NTOK * RANK];
__device__ float g_scores[16 * 1024 * 1024];
__device__ int   g_cnt_c[3 * NC];
__device__ int   g_list_c[3 * NC * NTOK];
__device__ float g_wt_c[3 * NC * NTOK];
__device__ int   g_cnt_e[NC];
__device__ int   g_list_e[NC * NTOK];
__device__ float g_wt_e[NC * NTOK];

// ---------------------------------------------------------------------------
// tf32 helpers: 3xTF32 split  f = hi + lo
// ---------------------------------------------------------------------------
__device__ __forceinline__ unsigned f2tf(float f) {
    unsigned u; asm("cvt.rna.tf32.f32 %0, %1;" : "=r"(u) : "f"(f)); return u;
}
__device__ __forceinline__ void st_split(unsigned* hi, unsigned* lo, float f) {
    const unsigned h = f2tf(f);
    *hi = h;
    *lo = f2tf(f - __uint_as_float(h));
}
__device__ __forceinline__ void split4(float4 v, uint4& hi, uint4& lo) {
    hi.x = f2tf(v.x); hi.y = f2tf(v.y); hi.z = f2tf(v.z); hi.w = f2tf(v.w);
    lo.x = f2tf(v.x - __uint_as_float(hi.x));
    lo.y = f2tf(v.y - __uint_as_float(hi.y));
    lo.z = f2tf(v.z - __uint_as_float(hi.z));
    lo.w = f2tf(v.w - __uint_as_float(hi.w));
}

__device__ __forceinline__ void mma8(float* c, unsigned a0, unsigned a1,
                                     unsigned a2, unsigned a3,
                                     unsigned b0, unsigned b1) {
    asm volatile(
        "mma.sync.aligned.m16n8k8.row.col.f32.tf32.tf32.f32 "
        "{%0,%1,%2,%3},{%4,%5,%6,%7},{%8,%9},{%0,%1,%2,%3};"
        : "+f"(c[0]), "+f"(c[1]), "+f"(c[2]), "+f"(c[3])
        : "r"(a0), "r"(a1), "r"(a2), "r"(a3), "r"(b0), "r"(b1));
}

__device__ __forceinline__ void cpa16(void* dst, const void* src) {
    unsigned d = (unsigned)__cvta_generic_to_shared(dst);
    asm volatile("cp.async.cg.shared.global [%0], [%1], 16;" :: "r"(d), "l"(src) : "memory");
}
__device__ __forceinline__ void cp_commit() {
    asm volatile("cp.async.commit_group;" ::: "memory");
}
__device__ __forceinline__ void cp_wait0() {
    asm volatile("cp.async.wait_group 0;" ::: "memory");
}

// One K=32 stage; warp tile m32 x n64, 3xTF32.
template<int AROWS, int BP>
__device__ __forceinline__ void compute_stage64(
    const unsigned* __restrict__ As, const unsigned* __restrict__ Bs,
    float acc[2][8][4], int wm, int wn, int gid, int tig)
{
    const int AO = AROWS * APITCH, BO = 32 * BP;
    #pragma unroll
    for (int ks = 0; ks < 4; ++ks) {
        const int k0 = ks * 8;
        unsigned ah[2][4], al[2][4];
        #pragma unroll
        for (int m = 0; m < 2; ++m) {
            const int r0 = (wm * 32 + m * 16 + gid) * APITCH + k0;
            const int r1 = (wm * 32 + m * 16 + gid + 8) * APITCH + k0;
            ah[m][0] = As[r0 + tig];          ah[m][1] = As[r1 + tig];
            ah[m][2] = As[r0 + tig + 4];      ah[m][3] = As[r1 + tig + 4];
            al[m][0] = As[AO + r0 + tig];     al[m][1] = As[AO + r1 + tig];
            al[m][2] = As[AO + r0 + tig + 4]; al[m][3] = As[AO + r1 + tig + 4];
        }
        #pragma unroll
        for (int t = 0; t < 8; ++t) {
            const int c0 = (k0 + tig) * BP + wn * 64 + t * 8 + gid;
            const int c1 = c0 + 4 * BP;
            const unsigned bh0 = Bs[c0],      bh1 = Bs[c1];
            const unsigned bl0 = Bs[BO + c0], bl1 = Bs[BO + c1];
            #pragma unroll
            for (int m = 0; m < 2; ++m) {
                mma8(acc[m][t], ah[m][0], ah[m][1], ah[m][2], ah[m][3], bl0, bl1);
                mma8(acc[m][t], al[m][0], al[m][1], al[m][2], al[m][3], bh0, bh1);
                mma8(acc[m][t], ah[m][0], ah[m][1], ah[m][2], ah[m][3], bh0, bh1);
            }
        }
    }
}

// ---------------------------------------------------------------------------
__global__ void k_zero(float* __restrict__ out) {
    const int idx = blockIdx.x * blockDim.x + threadIdx.x;
    const int stride = gridDim.x * blockDim.x;
    for (int i = idx; i < 3 * NTOK * RANK; i += stride) g_qkv[i] = 0.f;
    for (int i = idx; i < NTOK * DMODEL;  i += stride) out[i]   = 0.f;
    if (idx < 3 * NC) g_cnt_c[idx] = 0;
    if (idx < NC)     g_cnt_e[idx] = 0;
}

// ---------------------------------------------------------------------------
// Top-k + softmax + scatter (exact fp32)
// ---------------------------------------------------------------------------
__device__ __forceinline__ void topk_softmax_scatter(
    const float* __restrict__ s, int K, int li_base, int t,
    int* __restrict__ cnt, int* __restrict__ lists, float* __restrict__ wts)
{
    float vals[8]; int idxs[8];
    unsigned long long taken = 0ull;
    for (int kk = 0; kk < K; ++kk) {
        float best = -1e30f; int bi = 0;
        for (int nn = 0; nn < NC; ++nn) {
            const float v = s[nn];
            if (!((taken >> nn) & 1ull) && v > best) { best = v; bi = nn; }
        }
        taken |= 1ull << bi; vals[kk] = best; idxs[kk] = bi;
    }
    const float m = vals[0];
    float ex[8]; float sum = 0.f;
    for (int kk = 0; kk < K; ++kk) { ex[kk] = expf(vals[kk] - m); sum += ex[kk]; }
    const float inv = 1.f / sum;
    for (int kk = 0; kk < K; ++kk) {
        const int li = li_base + idxs[kk];
        const int slot = atomicAdd(&cnt[li], 1);
        lists[(size_t)li * NTOK + slot] = t;
        wts [(size_t)li * NTOK + slot] = ex[kk] * inv;
    }
}

// ---------------------------------------------------------------------------
__global__ __launch_bounds__(256) void k_router_c(
    const float* __restrict__ x, const float* __restrict__ wq,
    const float* __restrict__ wk, const float* __restrict__ wv)
{
    __shared__ float xs[8 * DMODEL];
    __shared__ float sc[8 * 192];
    const int t0 = blockIdx.x * 8;
    const int tid = threadIdx.x;
    for (int i = tid; i < 8 * DMODEL; i += 256) xs[i] = x[(size_t)t0 * DMODEL + i];
    __syncthreads();

    const int warp = tid >> 5, lane = tid & 31;
    const float* wr[3] = { wq, wk, wv };
    for (int j = warp; j < 192; j += 8) {
        const float* wrow = wr[j >> 6] + (size_t)(j & 63) * DMODEL;
        float acc[8] = {0,0,0,0,0,0,0,0};
        for (int i = lane; i < DMODEL; i += 32) {
            const float wv_ = wrow[i];
            #pragma unroll
            for (int tt = 0; tt < 8; ++tt) acc[tt] += xs[tt * DMODEL + i] * wv_;
        }
        #pragma unroll
        for (int tt = 0; tt < 8; ++tt) {
            float v = acc[tt];
            for (int o = 16; o; o >>= 1) v += __shfl_down_sync(0xffffffffu, v, o);
            if (lane == 0) sc[tt * 192 + j] = v;
        }
    }
    __syncthreads();

    if (tid < 24) {
        const int tt = tid / 3, p = tid % 3;
        topk_softmax_scatter(&sc[tt * 192 + p * 64], KC, p * 64, t0 + tt,
                             g_cnt_c, g_list_c, g_wt_c);
    }
}

__global__ __launch_bounds__(256) void k_router_e(const float* __restrict__ wo)
{
    __shared__ float xs[8 * RANK];
    __shared__ float sc[8 * 64];
    const int t0 = blockIdx.x * 8;
    const int tid = threadIdx.x;
    for (int i = tid; i < 8 * RANK; i += 256) xs[i] = g_attn[(size_t)t0 * RANK + i];
    __syncthreads();

    const int warp = tid >> 5, lane = tid & 31;
    for (int j = warp; j < 64; j += 8) {
        const float* wrow = wo + (size_t)j * RANK;
        float acc[8] = {0,0,0,0,0,0,0,0};
        for (int i = lane; i < RANK; i += 32) {
            const float wv_ = wrow[i];
            #pragma unroll
            for (int tt = 0; tt < 8; ++tt) acc[tt] += xs[tt * RANK + i] * wv_;
        }
        #pragma unroll
        for (int tt = 0; tt < 8; ++tt) {
            float v = acc[tt];
            for (int o = 16; o; o >>= 1) v += __shfl_down_sync(0xffffffffu, v, o);
            if (lane == 0) sc[tt * 64 + j] = v;
        }
    }
    __syncthreads();

    if (tid < 8)
        topk_softmax_scatter(&sc[tid * 64], KE, 0, t0 + tid,
                             g_cnt_e, g_list_e, g_wt_e);
}

// ---------------------------------------------------------------------------
// Gathered 3xTF32 MMA GEMM with cp.async software pipeline.
// CTA 128 x 128 x 32; 8 warps = 4(m) x 2(n) of m32n64.  (round-8 path)
// ---------------------------------------------------------------------------
template<int KA, int NOUT>
__device__ __forceinline__ void gemm_scatter_pipe(
    const float* __restrict__ Abase, const float* __restrict__ Bn,
    float* __restrict__ C, const int* __restrict__ tl,
    const float* __restrict__ wl, int c, int cb)
{
    extern __shared__ unsigned smem[];
    unsigned* As   = smem;                               // 2*128*APITCH
    unsigned* Bs   = As + 2 * 128 * APITCH;              // 2*32*BP128
    float*    rawA = (float*)(Bs + 2 * 32 * BP128);      // 128*APITCH
    float*    rawB = rawA + 128 * APITCH;                // 32*128
    int*      ts   = (int*)(rawB + 32 * 128);            // 128
    float*    ws   = (float*)(ts + 128);                 // 128
    const int tid = threadIdx.x, lane = tid & 31, warp = tid >> 5;
    const int wm = warp & 3, wn = warp >> 2;
    const int gid = lane >> 2, tig = lane & 3;
    const int S = KA / 32;

    for (int row0 = 0; row0 < c; row0 += 128) {
        const int rows = min(128, c - row0);
        __syncthreads();               // prior epilogue / raw reads done
        if (tid < 128) {
            ts[tid] = (tid < rows) ? tl[row0 + tid] : 0;
            ws[tid] = (tid < rows) ? wl[row0 + tid] : 0.f;
        }
        __syncthreads();               // ts visible before cp issue

        // prologue: stage 0 loads in flight
        #pragma unroll
        for (int i = 0; i < 4; ++i) {
            const int j = tid + 256 * i, r = j >> 3, q = j & 7;
            cpa16(&rawA[r * APITCH + q * 4],
                  Abase + (size_t)ts[r] * KA + q * 4);
        }
        #pragma unroll
        for (int i = 0; i < 4; ++i) {
            const int j = tid + 256 * i, kk = j >> 5, q = j & 31;
            cpa16(&rawB[kk * 128 + q * 4],
                  Bn + (size_t)kk * NOUT + cb + q * 4);
        }
        cp_commit();

        float acc[2][8][4] = {};
        for (int s = 0; s < S; ++s) {
            cp_wait0();
            __syncthreads();           // raw[s] visible; planes free

            // split raw -> operand planes
            #pragma unroll
            for (int i = 0; i < 4; ++i) {
                const int j = tid + 256 * i, r = j >> 3, q = j & 7;
                const float4 v = *(const float4*)&rawA[r * APITCH + q * 4];
                uint4 hi, lo; split4(v, hi, lo);
                *(uint4*)&As[r * APITCH + q * 4] = hi;
                *(uint4*)&As[128 * APITCH + r * APITCH + q * 4] = lo;
            }
            #pragma unroll
            for (int i = 0; i < 4; ++i) {
                const int j = tid + 256 * i, kk = j >> 5, q = j & 31;
                const float4 v = *(const float4*)&rawB[kk * 128 + q * 4];
                uint4 hi, lo; split4(v, hi, lo);
                *(uint4*)&Bs[kk * BP128 + q * 4] = hi;
                *(uint4*)&Bs[32 * BP128 + kk * BP128 + q * 4] = lo;
            }
            __syncthreads();           // planes ready; raw consumed

            // prefetch stage s+1 (overlaps compute below)
            if (s + 1 < S) {
                const int k0 = (s + 1) * 32;
                #pragma unroll
                for (int i = 0; i < 4; ++i) {
                    const int j = tid + 256 * i, r = j >> 3, q = j & 7;
                    cpa16(&rawA[r * APITCH + q * 4],
                          Abase + (size_t)ts[r] * KA + k0 + q * 4);
                }
                #pragma unroll
                for (int i = 0; i < 4; ++i) {
                    const int j = tid + 256 * i, kk = j >> 5, q = j & 31;
                    cpa16(&rawB[kk * 128 + q * 4],
                          Bn + (size_t)(k0 + kk) * NOUT + cb + q * 4);
                }
                cp_commit();
            }

            compute_stage64<128, BP128>(As, Bs, acc, wm, wn, gid, tig);
        }

        #pragma unroll
        for (int m = 0; m < 2; ++m)
        #pragma unroll
        for (int i = 0; i < 4; ++i) {
            const int r = wm * 32 + m * 16 + gid + ((i >> 1) ? 8 : 0);
            if (r < rows) {
                const float w = ws[r];
                float* crow = C + (size_t)ts[r] * NOUT + cb;
                #pragma unroll
                for (int t = 0; t < 8; ++t)
                    atomicAdd(&crow[wn * 64 + t * 8 + tig * 2 + (i & 1)],
                              w * acc[m][t][i]);
            }
        }
    }
}

__global__ __launch_bounds__(256) void k_gemm_compress(
    const float* __restrict__ x, const float* __restrict__ cn)
{
    const int li = blockIdx.y;
    const int n  = li & 63;
    gemm_scatter_pipe<DMODEL, RANK>(
        x, cn + (size_t)n * DMODEL * RANK,
        g_qkv + (size_t)(li >> 6) * NTOK * RANK,
        g_list_c + (size_t)li * NTOK, g_wt_c + (size_t)li * NTOK,
        g_cnt_c[li], blockIdx.x * 128);
}

__global__ __launch_bounds__(256) void k_gemm_expand(
    const float* __restrict__ en, float* __restrict__ out)
{
    const int li = blockIdx.y;
    gemm_scatter_pipe<RANK, DMODEL>(
        g_attn, en + (size_t)li * RANK * DMODEL, out,
        g_list_e + (size_t)li * NTOK, g_wt_e + (size_t)li * NTOK,
        g_cnt_e[li], blockIdx.x * 128);
}

// ---------------------------------------------------------------------------
// Attention scores = (Qh Kh^T)/8.  CTA 128x128 (round-8 known-good path)
// ---------------------------------------------------------------------------
__global__ __launch_bounds__(256) void k_attn_scores()
{
    const int bh = blockIdx.z, b = bh >> 3, h = bh & 7;
    const int i0 = blockIdx.y * 128, j0 = blockIdx.x * 128;
    const float* Qb = g_qkv + (size_t)b * 1024 * RANK + h * DHEAD;
    const float* Kb = g_qkv + (size_t)NTOK * RANK + (size_t)b * 1024 * RANK + h * DHEAD;
    extern __shared__ unsigned smem[];
    unsigned* As = smem;
    unsigned* Bs = smem + 2 * 128 * APITCH;
    const int tid = threadIdx.x, lane = tid & 31, warp = tid >> 5;
    const int wm = warp & 3, wn = warp >> 2;
    const int gid = lane >> 2, tig = lane & 3;

    float acc[2][8][4] = {};
    for (int k0 = 0; k0 < DHEAD; k0 += 32) {
        __syncthreads();
        #pragma unroll
        for (int e = tid; e < 1024; e += 256) {
            const int r = e >> 3, q = e & 7;
            const float4 v = *reinterpret_cast<const float4*>(
                Qb + (size_t)(i0 + r) * RANK + k0 + q * 4);
            uint4 hi, lo; split4(v, hi, lo);
            *(uint4*)&As[r * APITCH + q * 4] = hi;
            *(uint4*)&As[128 * APITCH + r * APITCH + q * 4] = lo;
        }
        #pragma unroll
        for (int e = tid; e < 1024; e += 256) {
            const int n = e >> 3, q = e & 7;
            const float4 v = *reinterpret_cast<const float4*>(
                Kb + (size_t)(j0 + n) * RANK + k0 + q * 4);
            st_split(&Bs[(q*4+0)*BP128 + n], &Bs[32*BP128 + (q*4+0)*BP128 + n], v.x);
            st_split(&Bs[(q*4+1)*BP128 + n], &Bs[32*BP128 + (q*4+1)*BP128 + n], v.y);
            st_split(&Bs[(q*4+2)*BP128 + n], &Bs[32*BP128 + (q*4+2)*BP128 + n], v.z);
            st_split(&Bs[(q*4+3)*BP128 + n], &Bs[32*BP128 + (q*4+3)*BP128 + n], v.w);
        }
        __syncthreads();
        compute_stage64<128, BP128>(As, Bs, acc, wm, wn, gid, tig);
    }
    float* outp = g_scores + (size_t)bh * 1024 * 1024;
    #pragma unroll
    for (int m = 0; m < 2; ++m)
    #pragma unroll
    for (int i = 0; i < 4; ++i) {
        const int r = i0 + wm * 32 + m * 16 + gid + ((i >> 1) ? 8 : 0);
        #pragma unroll
        for (int t = 0; t < 8; ++t)
            outp[(size_t)r * 1024 + j0 + wn * 64 + t * 8 + tig * 2 + (i & 1)] =
                acc[m][t][i] * 0.125f;
    }
}

// ---------------------------------------------------------------------------
__global__ __launch_bounds__(256) void k_softmax()
{
    float* p = g_scores + (size_t)blockIdx.x * 1024;
    __shared__ float red[256];
    const int tid = threadIdx.x;
    float m = -1e30f;
    for (int i = tid; i < 1024; i += 256) m = fmaxf(m, p[i]);
    red[tid] = m; __syncthreads();
    for (int s = 128; s; s >>= 1) { if (tid < s) red[tid] = fmaxf(red[tid], red[tid + s]); __syncthreads(); }
    m = red[0]; __syncthreads();
    float sum = 0.f;
    for (int i = tid; i < 1024; i += 256) { const float e = expf(p[i] - m); p[i] = e; sum += e; }
    red[tid] = sum; __syncthreads();
    for (int s = 128; s; s >>= 1) { if (tid < s) red[tid] += red[tid + s]; __syncthreads(); }
    const float inv = 1.f / red[0];
    for (int i = tid; i < 1024; i += 256) p[i] *= inv;
}

// ---------------------------------------------------------------------------
// attn_out = P @ V.  CTA 256x64; 8 warps m32n64 (wm=warp).  grid (4, 16)
// ---------------------------------------------------------------------------
__global__ __launch_bounds__(256) void k_attn_pv()
{
    const int bh = blockIdx.y, b = bh >> 3, h = bh & 7;
    const int i0 = blockIdx.x * 256;
    const float* P  = g_scores + (size_t)bh * 1024 * 1024;
    const float* Vb = g_qkv + (size_t)2 * NTOK * RANK + (size_t)b * 1024 * RANK + h * DHEAD;
    extern __shared__ unsigned smem[];
    unsigned* As = smem;
    unsigned* Bs = smem + 2 * 256 * APITCH;
    const int tid = threadIdx.x, lane = tid & 31, warp = tid >> 5;
    const int wm = warp;
    const int gid = lane >> 2, tig = lane & 3;

    float acc[2][8][4] = {};
    for (int k0 = 0; k0 < 1024; k0 += 32) {
        __syncthreads();
        #pragma unroll
        for (int e = tid; e < 2048; e += 256) {
            const int r = e >> 3, q = e & 7;
            const float4 v = *reinterpret_cast<const float4*>(
                P + (size_t)(i0 + r) * 1024 + k0 + q * 4);
            uint4 hi, lo; split4(v, hi, lo);
            *(uint4*)&As[r * APITCH + q * 4] = hi;
            *(uint4*)&As[256 * APITCH + r * APITCH + q * 4] = lo;
        }
        #pragma unroll
        for (int e = tid; e < 512; e += 256) {
            const int kk = e >> 4, q = e & 15;
            const float4 v = *reinterpret_cast<const float4*>(
                Vb + (size_t)(k0 + kk) * RANK + q * 4);
            uint4 hi, lo; split4(v, hi, lo);
            *(uint4*)&Bs[kk * BP64 + q * 4] = hi;
            *(uint4*)&Bs[32 * BP64 + kk * BP64 + q * 4] = lo;
        }
        __syncthreads();
        compute_stage64<256, BP64>(As, Bs, acc, wm, 0, gid, tig);
    }
    #pragma unroll
    for (int m = 0; m < 2; ++m)
    #pragma unroll
    for (int i = 0; i < 4; ++i) {
        const int r = b * 1024 + i0 + wm * 32 + m * 16 + gid + ((i >> 1) ? 8 : 0);
        #pragma unroll
        for (int t = 0; t < 8; ++t)
            g_attn[(size_t)r * RANK + h * DHEAD + t * 8 + tig * 2 + (i & 1)] =
                acc[m][t][i];
    }
}

// ---------------------------------------------------------------------------
extern "C" void kernel_launch(void* const* d_in, const int* in_sizes, int n_in,
                              void* d_out, int out_size)
{
    const float* x  = (const float*)d_in[0];
    const float* cn = (const float*)d_in[2];
    const float* en = (const float*)d_in[3];
    const float* wq = (const float*)d_in[4];
    const float* wv = (const float*)d_in[6];
    const float* wk = (const float*)d_in[5];
    const float* wo = (const float*)d_in[7];
    float* out = (float*)d_out;

    cudaFuncSetAttribute(k_gemm_compress, cudaFuncAttributeMaxDynamicSharedMemorySize, GEMM_SMEM_W * 4);
    cudaFuncSetAttribute(k_gemm_expand,   cudaFuncAttributeMaxDynamicSharedMemorySize, GEMM_SMEM_W * 4);
    cudaFuncSetAttribute(k_attn_scores,   cudaFuncAttributeMaxDynamicSharedMemorySize, SCORES_SMEM_W * 4);
    cudaFuncSetAttribute(k_attn_pv,       cudaFuncAttributeMaxDynamicSharedMemorySize, PV_SMEM_W * 4);

    // NOTE: k_zero launched twice (idempotent). This shifts k_gemm_compress
    // into ncu's capture slot (-s 5 -c 1) so the dominant kernel finally gets
    // profiled. Costs ~10us; round-8 configuration otherwise unchanged.
    k_zero<<<2048, 256>>>(out);
    k_zero<<<2048, 256>>>(out);
    k_router_c<<<NTOK / 8, 256>>>(x, wq, wk, wv);
    k_gemm_compress<<<dim3(4, 192), 256, GEMM_SMEM_W * 4>>>(x, cn);
    k_attn_scores<<<dim3(8, 8, 16), 256, SCORES_SMEM_W * 4>>>();
    k_softmax<<<16384, 256>>>();
    k_attn_pv<<<dim3(4, 16), 256, PV_SMEM_W * 4>>>();
    k_router_e<<<NTOK / 8, 256>>>(wo);
    k_gemm_expand<<<dim3(8, 64), 256, GEMM_SMEM_W * 4>>>(en, out);
}

// round 15
// speedup vs baseline: 1.3816x; 1.0359x over previous
#include <cuda_runtime.h>
#include <math.h>

// ---------------------------------------------------------------------------
// Problem constants
// ---------------------------------------------------------------------------
#define NTOK   2048
#define DMODEL 1024
#define RANK   512
#define NHEADS 8
#define DHEAD  64
#define NC     64
#define KC     8
#define KE     4

#define APITCH 36        // ≡4 (mod 32): A frag banks 4*gid+tig all distinct
#define BP128  136       // ≡8 (mod 32): B frag banks 8*tig+gid all distinct
#define BP64   72        // ≡8 (mod 32), n-tile 64 (PV)

#define RAW_A (128 * APITCH)   // 4608 words per A buffer
#define RAW_B (32 * BP128)     // 4352 words per B buffer
// GEMM v6 smem: rawA x2 (hi planes) + rawB x2 + loA + loB + ts/ws
#define GEMM_SMEM_W   (2 * RAW_A + 2 * RAW_B + RAW_A + RAW_B + 256)   // 27136 w = 108.5 KB
#define SCORES_SMEM_W (2 * 128 * APITCH + 2 * 32 * BP128)
#define PV_SMEM_W     (2 * 256 * APITCH + 2 * 32 * BP64)

// ---------------------------------------------------------------------------
// Device scratch
// ---------------------------------------------------------------------------
__device__ float g_qkv[3 * NTOK * RANK];
__device__ float g_attn[NTOK * RANK];
__device__ float g_scores[16 * 1024 * 1024];
__device__ int   g_cnt_c[3 * NC];
__device__ int   g_list_c[3 * NC * NTOK];
__device__ float g_wt_c[3 * NC * NTOK];
__device__ int   g_cnt_e[NC];
__device__ int   g_list_e[NC * NTOK];
__device__ float g_wt_e[NC * NTOK];

// ---------------------------------------------------------------------------
// tf32 helpers
// ---------------------------------------------------------------------------
__device__ __forceinline__ unsigned f2tf(float f) {
    unsigned u; asm("cvt.rna.tf32.f32 %0, %1;" : "=r"(u) : "f"(f)); return u;
}
__device__ __forceinline__ void st_split(unsigned* hi, unsigned* lo, float f) {
    const unsigned h = f2tf(f);
    *hi = h;
    *lo = f2tf(f - __uint_as_float(h));
}
__device__ __forceinline__ void split4(float4 v, uint4& hi, uint4& lo) {
    hi.x = f2tf(v.x); hi.y = f2tf(v.y); hi.z = f2tf(v.z); hi.w = f2tf(v.w);
    lo.x = f2tf(v.x - __uint_as_float(hi.x));
    lo.y = f2tf(v.y - __uint_as_float(hi.y));
    lo.z = f2tf(v.z - __uint_as_float(hi.z));
    lo.w = f2tf(v.w - __uint_as_float(hi.w));
}
// RZ residual: lo = f - trunc_tf32(f).  Exact (Sterbenz); HW truncates lo too.
__device__ __forceinline__ unsigned lo_rz(float f) {
    const unsigned h = __float_as_uint(f) & 0xFFFFE000u;
    return __float_as_uint(f - __uint_as_float(h));
}
__device__ __forceinline__ uint4 lo_rz4(uint4 vbits) {
    uint4 r;
    r.x = lo_rz(__uint_as_float(vbits.x));
    r.y = lo_rz(__uint_as_float(vbits.y));
    r.z = lo_rz(__uint_as_float(vbits.z));
    r.w = lo_rz(__uint_as_float(vbits.w));
    return r;
}

__device__ __forceinline__ void mma8(float* c, unsigned a0, unsigned a1,
                                     unsigned a2, unsigned a3,
                                     unsigned b0, unsigned b1) {
    asm volatile(
        "mma.sync.aligned.m16n8k8.row.col.f32.tf32.tf32.f32 "
        "{%0,%1,%2,%3},{%4,%5,%6,%7},{%8,%9},{%0,%1,%2,%3};"
        : "+f"(c[0]), "+f"(c[1]), "+f"(c[2]), "+f"(c[3])
        : "r"(a0), "r"(a1), "r"(a2), "r"(a3), "r"(b0), "r"(b1));
}

__device__ __forceinline__ void cpa16(void* dst, const void* src) {
    unsigned d = (unsigned)__cvta_generic_to_shared(dst);
    asm volatile("cp.async.cg.shared.global [%0], [%1], 16;" :: "r"(d), "l"(src) : "memory");
}
__device__ __forceinline__ void cp_commit() {
    asm volatile("cp.async.commit_group;" ::: "memory");
}
__device__ __forceinline__ void cp_wait0() {
    asm volatile("cp.async.wait_group 0;" ::: "memory");
}

// ---------------------------------------------------------------------------
// K=32 stage: hi operands read RAW f32 (HW truncates to tf32), lo from planes.
// Warp m32 x n64.  Same MMA order as round 8.
// ---------------------------------------------------------------------------
__device__ __forceinline__ void compute_stage_hz(
    const unsigned* __restrict__ hiA, const unsigned* __restrict__ hiB,
    const unsigned* __restrict__ loA, const unsigned* __restrict__ loB,
    float acc[2][8][4], int wm, int wn, int gid, int tig)
{
    #pragma unroll
    for (int ks = 0; ks < 4; ++ks) {
        const int k0 = ks * 8;
        unsigned ah[2][4], al[2][4];
        #pragma unroll
        for (int m = 0; m < 2; ++m) {
            const int r0 = (wm * 32 + m * 16 + gid) * APITCH + k0;
            const int r1 = r0 + 8 * APITCH;
            ah[m][0] = hiA[r0 + tig];     ah[m][1] = hiA[r1 + tig];
            ah[m][2] = hiA[r0 + tig + 4]; ah[m][3] = hiA[r1 + tig + 4];
            al[m][0] = loA[r0 + tig];     al[m][1] = loA[r1 + tig];
            al[m][2] = loA[r0 + tig + 4]; al[m][3] = loA[r1 + tig + 4];
        }
        #pragma unroll
        for (int t = 0; t < 8; ++t) {
            const int c0 = (k0 + tig) * BP128 + wn * 64 + t * 8 + gid;
            const int c1 = c0 + 4 * BP128;
            const unsigned bh0 = hiB[c0], bh1 = hiB[c1];
            const unsigned bl0 = loB[c0], bl1 = loB[c1];
            #pragma unroll
            for (int m = 0; m < 2; ++m) {
                mma8(acc[m][t], ah[m][0], ah[m][1], ah[m][2], ah[m][3], bl0, bl1);
                mma8(acc[m][t], al[m][0], al[m][1], al[m][2], al[m][3], bh0, bh1);
                mma8(acc[m][t], ah[m][0], ah[m][1], ah[m][2], ah[m][3], bh0, bh1);
            }
        }
    }
}

// K=32 stage for attention kernels (round-8 known-good path)
template<int AROWS, int BP>
__device__ __forceinline__ void compute_stage64(
    const unsigned* __restrict__ As, const unsigned* __restrict__ Bs,
    float acc[2][8][4], int wm, int wn, int gid, int tig)
{
    const int AO = AROWS * APITCH, BO = 32 * BP;
    #pragma unroll
    for (int ks = 0; ks < 4; ++ks) {
        const int k0 = ks * 8;
        unsigned ah[2][4], al[2][4];
        #pragma unroll
        for (int m = 0; m < 2; ++m) {
            const int r0 = (wm * 32 + m * 16 + gid) * APITCH + k0;
            const int r1 = (wm * 32 + m * 16 + gid + 8) * APITCH + k0;
            ah[m][0] = As[r0 + tig];          ah[m][1] = As[r1 + tig];
            ah[m][2] = As[r0 + tig + 4];      ah[m][3] = As[r1 + tig + 4];
            al[m][0] = As[AO + r0 + tig];     al[m][1] = As[AO + r1 + tig];
            al[m][2] = As[AO + r0 + tig + 4]; al[m][3] = As[AO + r1 + tig + 4];
        }
        #pragma unroll
        for (int t = 0; t < 8; ++t) {
            const int c0 = (k0 + tig) * BP + wn * 64 + t * 8 + gid;
            const int c1 = c0 + 4 * BP;
            const unsigned bh0 = Bs[c0],      bh1 = Bs[c1];
            const unsigned bl0 = Bs[BO + c0], bl1 = Bs[BO + c1];
            #pragma unroll
            for (int m = 0; m < 2; ++m) {
                mma8(acc[m][t], ah[m][0], ah[m][1], ah[m][2], ah[m][3], bl0, bl1);
                mma8(acc[m][t], al[m][0], al[m][1], al[m][2], al[m][3], bh0, bh1);
                mma8(acc[m][t], ah[m][0], ah[m][1], ah[m][2], ah[m][3], bh0, bh1);
            }
        }
    }
}

// ---------------------------------------------------------------------------
__global__ void k_zero(float* __restrict__ out) {
    const int idx = blockIdx.x * blockDim.x + threadIdx.x;
    const int stride = gridDim.x * blockDim.x;
    for (int i = idx; i < 3 * NTOK * RANK; i += stride) g_qkv[i] = 0.f;
    for (int i = idx; i < NTOK * DMODEL;  i += stride) out[i]   = 0.f;
    if (idx < 3 * NC) g_cnt_c[idx] = 0;
    if (idx < NC)     g_cnt_e[idx] = 0;
}

// ---------------------------------------------------------------------------
// Top-k + softmax + scatter (exact fp32)
// ---------------------------------------------------------------------------
__device__ __forceinline__ void topk_softmax_scatter(
    const float* __restrict__ s, int K, int li_base, int t,
    int* __restrict__ cnt, int* __restrict__ lists, float* __restrict__ wts)
{
    float vals[8]; int idxs[8];
    unsigned long long taken = 0ull;
    for (int kk = 0; kk < K; ++kk) {
        float best = -1e30f; int bi = 0;
        for (int nn = 0; nn < NC; ++nn) {
            const float v = s[nn];
            if (!((taken >> nn) & 1ull) && v > best) { best = v; bi = nn; }
        }
        taken |= 1ull << bi; vals[kk] = best; idxs[kk] = bi;
    }
    const float m = vals[0];
    float ex[8]; float sum = 0.f;
    for (int kk = 0; kk < K; ++kk) { ex[kk] = expf(vals[kk] - m); sum += ex[kk]; }
    const float inv = 1.f / sum;
    for (int kk = 0; kk < K; ++kk) {
        const int li = li_base + idxs[kk];
        const int slot = atomicAdd(&cnt[li], 1);
        lists[(size_t)li * NTOK + slot] = t;
        wts [(size_t)li * NTOK + slot] = ex[kk] * inv;
    }
}

// ---------------------------------------------------------------------------
__global__ __launch_bounds__(256) void k_router_c(
    const float* __restrict__ x, const float* __restrict__ wq,
    const float* __restrict__ wk, const float* __restrict__ wv)
{
    __shared__ float xs[8 * DMODEL];
    __shared__ float sc[8 * 192];
    const int t0 = blockIdx.x * 8;
    const int tid = threadIdx.x;
    for (int i = tid; i < 8 * DMODEL; i += 256) xs[i] = x[(size_t)t0 * DMODEL + i];
    __syncthreads();

    const int warp = tid >> 5, lane = tid & 31;
    const float* wr[3] = { wq, wk, wv };
    for (int j = warp; j < 192; j += 8) {
        const float* wrow = wr[j >> 6] + (size_t)(j & 63) * DMODEL;
        float acc[8] = {0,0,0,0,0,0,0,0};
        for (int i = lane; i < DMODEL; i += 32) {
            const float wv_ = wrow[i];
            #pragma unroll
            for (int tt = 0; tt < 8; ++tt) acc[tt] += xs[tt * DMODEL + i] * wv_;
        }
        #pragma unroll
        for (int tt = 0; tt < 8; ++tt) {
            float v = acc[tt];
            for (int o = 16; o; o >>= 1) v += __shfl_down_sync(0xffffffffu, v, o);
            if (lane == 0) sc[tt * 192 + j] = v;
        }
    }
    __syncthreads();

    if (tid < 24) {
        const int tt = tid / 3, p = tid % 3;
        topk_softmax_scatter(&sc[tt * 192 + p * 64], KC, p * 64, t0 + tt,
                             g_cnt_c, g_list_c, g_wt_c);
    }
}

__global__ __launch_bounds__(256) void k_router_e(const float* __restrict__ wo)
{
    __shared__ float xs[8 * RANK];
    __shared__ float sc[8 * 64];
    const int t0 = blockIdx.x * 8;
    const int tid = threadIdx.x;
    for (int i = tid; i < 8 * RANK; i += 256) xs[i] = g_attn[(size_t)t0 * RANK + i];
    __syncthreads();

    const int warp = tid >> 5, lane = tid & 31;
    for (int j = warp; j < 64; j += 8) {
        const float* wrow = wo + (size_t)j * RANK;
        float acc[8] = {0,0,0,0,0,0,0,0};
        for (int i = lane; i < RANK; i += 32) {
            const float wv_ = wrow[i];
            #pragma unroll
            for (int tt = 0; tt < 8; ++tt) acc[tt] += xs[tt * RANK + i] * wv_;
        }
        #pragma unroll
        for (int tt = 0; tt < 8; ++tt) {
            float v = acc[tt];
            for (int o = 16; o; o >>= 1) v += __shfl_down_sync(0xffffffffu, v, o);
            if (lane == 0) sc[tt * 64 + j] = v;
        }
    }
    __syncthreads();

    if (tid < 8)
        topk_softmax_scatter(&sc[tid * 64], KE, 0, t0 + tid,
                             g_cnt_e, g_list_e, g_wt_e);
}

// ---------------------------------------------------------------------------
// Gathered 3xTF32 MMA GEMM v6: raw buffers double as hi planes (HW tf32
// truncation); split computes only the lo residual (LOP3+FSUB).
// CTA 128 x 128 x 32; 8 warps = 4(m) x 2(n) of m32n64.
// ---------------------------------------------------------------------------
template<int KA, int NOUT>
__device__ __forceinline__ void gemm_scatter_pipe(
    const float* __restrict__ Abase, const float* __restrict__ Bn,
    float* __restrict__ C, const int* __restrict__ tl,
    const float* __restrict__ wl, int c, int cb)
{
    extern __shared__ unsigned smem[];
    unsigned* rawA = smem;                       // 2 * RAW_A (hi planes)
    unsigned* rawB = rawA + 2 * RAW_A;           // 2 * RAW_B
    unsigned* loA  = rawB + 2 * RAW_B;           // RAW_A
    unsigned* loB  = loA + RAW_A;                // RAW_B
    int*      ts   = (int*)(loB + RAW_B);        // 128
    float*    ws   = (float*)(ts + 128);         // 128
    const int tid = threadIdx.x, lane = tid & 31, warp = tid >> 5;
    const int wm = warp & 3, wn = warp >> 2;
    const int gid = lane >> 2, tig = lane & 3;
    const int S = KA / 32;

    for (int row0 = 0; row0 < c; row0 += 128) {
        const int rows = min(128, c - row0);
        __syncthreads();               // prior epilogue / buffers free
        if (tid < 128) {
            ts[tid] = (tid < rows) ? tl[row0 + tid] : 0;
            ws[tid] = (tid < rows) ? wl[row0 + tid] : 0.f;
        }
        __syncthreads();               // ts visible before cp issue

        #define FILL_STAGE(BUF, K0)                                            \
        {                                                                      \
            unsigned* ra = rawA + (BUF) * RAW_A;                               \
            unsigned* rb = rawB + (BUF) * RAW_B;                               \
            _Pragma("unroll")                                                  \
            for (int i = 0; i < 4; ++i) {                                      \
                const int j = tid + 256 * i, r = j >> 3, q = j & 7;            \
                cpa16(&ra[r * APITCH + q * 4],                                 \
                      Abase + (size_t)ts[r] * KA + (K0) + q * 4);              \
            }                                                                  \
            _Pragma("unroll")                                                  \
            for (int i = 0; i < 4; ++i) {                                      \
                const int j = tid + 256 * i, kk = j >> 5, q = j & 31;          \
                cpa16(&rb[kk * BP128 + q * 4],                                 \
                      Bn + (size_t)((K0) + kk) * NOUT + cb + q * 4);           \
            }                                                                  \
            cp_commit();                                                       \
        }

        FILL_STAGE(0, 0);              // prologue

        float acc[2][8][4] = {};
        for (int s = 0; s < S; ++s) {
            const int buf = s & 1;
            cp_wait0();                // raw[s] landed
            __syncthreads();           // + compute(s-1) done (lo planes free)

            // split: lo residual only (hi = raw, truncated by MMA datapath)
            {
                const unsigned* ra = rawA + buf * RAW_A;
                const unsigned* rb = rawB + buf * RAW_B;
                #pragma unroll
                for (int i = 0; i < 4; ++i) {
                    const int j = tid + 256 * i, r = j >> 3, q = j & 7;
                    const uint4 v = *(const uint4*)&ra[r * APITCH + q * 4];
                    *(uint4*)&loA[r * APITCH + q * 4] = lo_rz4(v);
                }
                #pragma unroll
                for (int i = 0; i < 4; ++i) {
                    const int j = tid + 256 * i, kk = j >> 5, q = j & 31;
                    const uint4 v = *(const uint4*)&rb[kk * BP128 + q * 4];
                    *(uint4*)&loB[kk * BP128 + q * 4] = lo_rz4(v);
                }
            }

            // prefetch stage s+1 into the other raw buffer (overlaps compute)
            if (s + 1 < S) FILL_STAGE(buf ^ 1, (s + 1) * 32);

            __syncthreads();           // lo planes visible
            compute_stage_hz(rawA + buf * RAW_A, rawB + buf * RAW_B,
                             loA, loB, acc, wm, wn, gid, tig);
        }

        #pragma unroll
        for (int m = 0; m < 2; ++m)
        #pragma unroll
        for (int i = 0; i < 4; ++i) {
            const int r = wm * 32 + m * 16 + gid + ((i >> 1) ? 8 : 0);
            if (r < rows) {
                const float w = ws[r];
                float* crow = C + (size_t)ts[r] * NOUT + cb;
                #pragma unroll
                for (int t = 0; t < 8; ++t)
                    atomicAdd(&crow[wn * 64 + t * 8 + tig * 2 + (i & 1)],
                              w * acc[m][t][i]);
            }
        }
        #undef FILL_STAGE
    }
}

__global__ __launch_bounds__(256) void k_gemm_compress(
    const float* __restrict__ x, const float* __restrict__ cn)
{
    const int li = blockIdx.y;
    const int n  = li & 63;
    gemm_scatter_pipe<DMODEL, RANK>(
        x, cn + (size_t)n * DMODEL * RANK,
        g_qkv + (size_t)(li >> 6) * NTOK * RANK,
        g_list_c + (size_t)li * NTOK, g_wt_c + (size_t)li * NTOK,
        g_cnt_c[li], blockIdx.x * 128);
}

__global__ __launch_bounds__(256) void k_gemm_expand(
    const float* __restrict__ en, float* __restrict__ out)
{
    const int li = blockIdx.y;
    gemm_scatter_pipe<RANK, DMODEL>(
        g_attn, en + (size_t)li * RANK * DMODEL, out,
        g_list_e + (size_t)li * NTOK, g_wt_e + (size_t)li * NTOK,
        g_cnt_e[li], blockIdx.x * 128);
}

// ---------------------------------------------------------------------------
// Attention scores = (Qh Kh^T)/8.  CTA 128x128 (round-8 known-good path)
// ---------------------------------------------------------------------------
__global__ __launch_bounds__(256) void k_attn_scores()
{
    const int bh = blockIdx.z, b = bh >> 3, h = bh & 7;
    const int i0 = blockIdx.y * 128, j0 = blockIdx.x * 128;
    const float* Qb = g_qkv + (size_t)b * 1024 * RANK + h * DHEAD;
    const float* Kb = g_qkv + (size_t)NTOK * RANK + (size_t)b * 1024 * RANK + h * DHEAD;
    extern __shared__ unsigned smemu[];
    unsigned* As = smemu;
    unsigned* Bs = smemu + 2 * 128 * APITCH;
    const int tid = threadIdx.x, lane = tid & 31, warp = tid >> 5;
    const int wm = warp & 3, wn = warp >> 2;
    const int gid = lane >> 2, tig = lane & 3;

    float acc[2][8][4] = {};
    for (int k0 = 0; k0 < DHEAD; k0 += 32) {
        __syncthreads();
        #pragma unroll
        for (int e = tid; e < 1024; e += 256) {
            const int r = e >> 3, q = e & 7;
            const float4 v = *reinterpret_cast<const float4*>(
                Qb + (size_t)(i0 + r) * RANK + k0 + q * 4);
            uint4 hi, lo; split4(v, hi, lo);
            *(uint4*)&As[r * APITCH + q * 4] = hi;
            *(uint4*)&As[128 * APITCH + r * APITCH + q * 4] = lo;
        }
        #pragma unroll
        for (int e = tid; e < 1024; e += 256) {
            const int n = e >> 3, q = e & 7;
            const float4 v = *reinterpret_cast<const float4*>(
                Kb + (size_t)(j0 + n) * RANK + k0 + q * 4);
            st_split(&Bs[(q*4+0)*BP128 + n], &Bs[32*BP128 + (q*4+0)*BP128 + n], v.x);
            st_split(&Bs[(q*4+1)*BP128 + n], &Bs[32*BP128 + (q*4+1)*BP128 + n], v.y);
            st_split(&Bs[(q*4+2)*BP128 + n], &Bs[32*BP128 + (q*4+2)*BP128 + n], v.z);
            st_split(&Bs[(q*4+3)*BP128 + n], &Bs[32*BP128 + (q*4+3)*BP128 + n], v.w);
        }
        __syncthreads();
        compute_stage64<128, BP128>(As, Bs, acc, wm, wn, gid, tig);
    }
    float* outp = g_scores + (size_t)bh * 1024 * 1024;
    #pragma unroll
    for (int m = 0; m < 2; ++m)
    #pragma unroll
    for (int i = 0; i < 4; ++i) {
        const int r = i0 + wm * 32 + m * 16 + gid + ((i >> 1) ? 8 : 0);
        #pragma unroll
        for (int t = 0; t < 8; ++t)
            outp[(size_t)r * 1024 + j0 + wn * 64 + t * 8 + tig * 2 + (i & 1)] =
                acc[m][t][i] * 0.125f;
    }
}

// ---------------------------------------------------------------------------
__global__ __launch_bounds__(256) void k_softmax()
{
    float* p = g_scores + (size_t)blockIdx.x * 1024;
    __shared__ float red[256];
    const int tid = threadIdx.x;
    float m = -1e30f;
    for (int i = tid; i < 1024; i += 256) m = fmaxf(m, p[i]);
    red[tid] = m; __syncthreads();
    for (int s = 128; s; s >>= 1) { if (tid < s) red[tid] = fmaxf(red[tid], red[tid + s]); __syncthreads(); }
    m = red[0]; __syncthreads();
    float sum = 0.f;
    for (int i = tid; i < 1024; i += 256) { const float e = expf(p[i] - m); p[i] = e; sum += e; }
    red[tid] = sum; __syncthreads();
    for (int s = 128; s; s >>= 1) { if (tid < s) red[tid] += red[tid + s]; __syncthreads(); }
    const float inv = 1.f / red[0];
    for (int i = tid; i < 1024; i += 256) p[i] *= inv;
}

// ---------------------------------------------------------------------------
// attn_out = P @ V.  CTA 256x64 (round-8 known-good path)
// ---------------------------------------------------------------------------
__global__ __launch_bounds__(256) void k_attn_pv()
{
    const int bh = blockIdx.y, b = bh >> 3, h = bh & 7;
    const int i0 = blockIdx.x * 256;
    const float* P  = g_scores + (size_t)bh * 1024 * 1024;
    const float* Vb = g_qkv + (size_t)2 * NTOK * RANK + (size_t)b * 1024 * RANK + h * DHEAD;
    extern __shared__ unsigned smemu[];
    unsigned* As = smemu;
    unsigned* Bs = smemu + 2 * 256 * APITCH;
    const int tid = threadIdx.x, lane = tid & 31, warp = tid >> 5;
    const int wm = warp;
    const int gid = lane >> 2, tig = lane & 3;

    float acc[2][8][4] = {};
    for (int k0 = 0; k0 < 1024; k0 += 32) {
        __syncthreads();
        #pragma unroll
        for (int e = tid; e < 2048; e += 256) {
            const int r = e >> 3, q = e & 7;
            const float4 v = *reinterpret_cast<const float4*>(
                P + (size_t)(i0 + r) * 1024 + k0 + q * 4);
            uint4 hi, lo; split4(v, hi, lo);
            *(uint4*)&As[r * APITCH + q * 4] = hi;
            *(uint4*)&As[256 * APITCH + r * APITCH + q * 4] = lo;
        }
        #pragma unroll
        for (int e = tid; e < 512; e += 256) {
            const int kk = e >> 4, q = e & 15;
            const float4 v = *reinterpret_cast<const float4*>(
                Vb + (size_t)(k0 + kk) * RANK + q * 4);
            uint4 hi, lo; split4(v, hi, lo);
            *(uint4*)&Bs[kk * BP64 + q * 4] = hi;
            *(uint4*)&Bs[32 * BP64 + kk * BP64 + q * 4] = lo;
        }
        __syncthreads();
        compute_stage64<256, BP64>(As, Bs, acc, wm, 0, gid, tig);
    }
    #pragma unroll
    for (int m = 0; m < 2; ++m)
    #pragma unroll
    for (int i = 0; i < 4; ++i) {
        const int r = b * 1024 + i0 + wm * 32 + m * 16 + gid + ((i >> 1) ? 8 : 0);
        #pragma unroll
        for (int t = 0; t < 8; ++t)
            g_attn[(size_t)r * RANK + h * DHEAD + t * 8 + tig * 2 + (i & 1)] =
                acc[m][t][i];
    }
}

// ---------------------------------------------------------------------------
extern "C" void kernel_launch(void* const* d_in, const int* in_sizes, int n_in,
                              void* d_out, int out_size)
{
    const float* x  = (const float*)d_in[0];
    const float* cn = (const float*)d_in[2];
    const float* en = (const float*)d_in[3];
    const float* wq = (const float*)d_in[4];
    const float* wk = (const float*)d_in[5];
    const float* wv = (const float*)d_in[6];
    const float* wo = (const float*)d_in[7];
    float* out = (float*)d_out;

    cudaFuncSetAttribute(k_gemm_compress, cudaFuncAttributeMaxDynamicSharedMemorySize, GEMM_SMEM_W * 4);
    cudaFuncSetAttribute(k_gemm_expand,   cudaFuncAttributeMaxDynamicSharedMemorySize, GEMM_SMEM_W * 4);
    cudaFuncSetAttribute(k_attn_scores,   cudaFuncAttributeMaxDynamicSharedMemorySize, SCORES_SMEM_W * 4);
    cudaFuncSetAttribute(k_attn_pv,       cudaFuncAttributeMaxDynamicSharedMemorySize, PV_SMEM_W * 4);

    // double k_zero keeps k_gemm_compress in ncu's capture slot
    k_zero<<<2048, 256>>>(out);
    k_zero<<<2048, 256>>>(out);
    k_router_c<<<NTOK / 8, 256>>>(x, wq, wk, wv);
    k_gemm_compress<<<dim3(4, 192), 256, GEMM_SMEM_W * 4>>>(x, cn);
    k_attn_scores<<<dim3(8, 8, 16), 256, SCORES_SMEM_W * 4>>>();
    k_softmax<<<16384, 256>>>();
    k_attn_pv<<<dim3(4, 16), 256, PV_SMEM_W * 4>>>();
    k_router_e<<<NTOK / 8, 256>>>(wo);
    k_gemm_expand<<<dim3(8, 64), 256, GEMM_SMEM_W * 4>>>(en, out);
}